// round 14
// baseline (speedup 1.0000x reference)
#include <cuda_runtime.h>
#include <cuda_fp16.h>
#include <math.h>
#include <stdint.h>

#define Bn 8
#define Nn 8192
#define Cn 256
#define Hn 4
#define Dn 64
#define BHn (Bn*Hn)
#define MTOT (Bn*Nn)
#define GSP 8
#define GSL (Nn/GSP)       // 1024
#define NCTAQ (MTOT/64)    // 1024 (GEMM CTAs per operand)

// ---------------------------------------------------------------------------
// Scratch (__device__ globals; no allocation allowed)
// ---------------------------------------------------------------------------
__device__ __half g_qh [MTOT*Cn];
__device__ __half g_kh [MTOT*Cn];
__device__ __half g_wh [2*Cn*Cn];
__device__ __half g_w2h[Bn*Cn*Cn];
__device__ float  g_u  [Bn*Cn*Cn];
__device__ float  g_gp [BHn*GSP*Dn*Dn];
__device__ float  g_attn[BHn*Dn*Dn];
__device__ float  g_nssp[2*NCTAQ*Cn];
__device__ float  g_nss2[2*Bn*Cn];

// ---------------------------------------------------------------------------
// Helpers
// ---------------------------------------------------------------------------
__device__ __forceinline__ uint32_t smem_u32(const void* p) {
    uint32_t a;
    asm("{ .reg .u64 t; cvta.to.shared.u64 t, %1; cvt.u32.u64 %0, t; }" : "=r"(a) : "l"(p));
    return a;
}
__device__ __forceinline__ void cp16(uint32_t sdst, const void* gsrc) {
    asm volatile("cp.async.cg.shared.global [%0], [%1], 16;"
                 :: "r"(sdst), "l"(__cvta_generic_to_global(gsrc)) : "memory");
}
#define CP_COMMIT() asm volatile("cp.async.commit_group;" ::: "memory")
#define CP_WAIT2()  asm volatile("cp.async.wait_group 2;" ::: "memory")

#define LDSM4(r0, r1, r2, r3, addr) \
    asm volatile("ldmatrix.sync.aligned.m8n8.x4.shared.b16 {%0,%1,%2,%3}, [%4];" \
                 : "=r"(r0), "=r"(r1), "=r"(r2), "=r"(r3) : "r"(addr))
#define LDSM4T(r0, r1, r2, r3, addr) \
    asm volatile("ldmatrix.sync.aligned.m8n8.x4.trans.shared.b16 {%0,%1,%2,%3}, [%4];" \
                 : "=r"(r0), "=r"(r1), "=r"(r2), "=r"(r3) : "r"(addr))
#define LDSM2T(r0, r1, addr) \
    asm volatile("ldmatrix.sync.aligned.m8n8.x2.trans.shared.b16 {%0,%1}, [%2];" \
                 : "=r"(r0), "=r"(r1) : "r"(addr))

__device__ __forceinline__ void mma_f16(float* d, const uint32_t* a, const uint32_t* b) {
    asm volatile(
        "mma.sync.aligned.m16n8k16.row.col.f32.f16.f16.f32 "
        "{%0,%1,%2,%3}, {%4,%5,%6,%7}, {%8,%9}, {%0,%1,%2,%3};"
        : "+f"(d[0]), "+f"(d[1]), "+f"(d[2]), "+f"(d[3])
        : "r"(a[0]), "r"(a[1]), "r"(a[2]), "r"(a[3]), "r"(b[0]), "r"(b[1]));
}

// ---------------------------------------------------------------------------
// fp16 mma GEMM, fp32 A converted in-flight. CTA tile 64x256, 256 threads,
// 8 warps (2M x 4N, warp tile 32x64). K=256 in 8 chunks of 32, 4 stages.
// 2 CTAs/SM for latency hiding. Round-9 ordering inside the loop.
// ---------------------------------------------------------------------------
#define RSH 40
#define A_STG (64*RSH*2)                 // 5120 B
#define B_STG (256*RSH*2)                // 20480 B
#define NST 4
#define SMEM_T (NST*(A_STG+B_STG) + 2048) // 104448 B

template<bool OUTF32>
__global__ void __launch_bounds__(256, 2) gemm_h(const float* __restrict__ X0,
                                                 const __half* __restrict__ W0,
                                                 __half* __restrict__ Yh0,
                                                 const float* __restrict__ X1,
                                                 const __half* __restrict__ W1,
                                                 __half* __restrict__ Yh1,
                                                 const float* __restrict__ bias,
                                                 float* __restrict__ Yf,
                                                 float* __restrict__ nssp)
{
    extern __shared__ char sm[];
    const uint32_t sA = smem_u32(sm);
    const uint32_t sB = sA + NST * A_STG;
    float* part = reinterpret_cast<float*>(sm + NST * (A_STG + B_STG));

    const int tid  = threadIdx.x;
    const int wid  = tid >> 5, lane = tid & 31;
    const int wm   = wid & 1;          // 2 M groups of 32
    const int wn   = wid >> 1;         // 4 N groups of 64
    const int gid  = lane >> 2;
    const int tig  = lane & 3;
    const int m0   = blockIdx.x * 64;
    const int z    = OUTF32 ? 0 : blockIdx.z;

    const float* X = (!OUTF32 && z) ? X1 : X0;
    const __half* Wp = OUTF32 ? W0 + ((size_t)(m0 >> 13) << 16) : (z ? W1 : W0);
    __half* Yh = z ? Yh1 : Yh0;

    const int lrA = ((lane >> 3) & 1) * 8 + (lane & 7);
    const int lkA = (lane >> 4) * 8;
    const int lrB = (lane >> 4) * 8 + (lane & 7);
    const int lkB = ((lane >> 3) & 1) * 8;
    int aoffs[2], boffs[4];
    #pragma unroll
    for (int mt = 0; mt < 2; mt++) aoffs[mt] = (wm * 32 + mt * 16 + lrA) * RSH + lkA;
    #pragma unroll
    for (int nb = 0; nb < 4; nb++) boffs[nb] = (wn * 64 + nb * 16 + lrB) * RSH + lkB;

    // A: 64 rows x 32 fp32 per chunk = 512 float4; 2 per thread
    auto ldA2 = [&](int k0, float4* p) {
        #pragma unroll
        for (int i = 0; i < 2; i++) {
            int g = tid + i * 256;
            p[i] = *reinterpret_cast<const float4*>(
                X + (size_t)(m0 + (g >> 3)) * Cn + k0 + (g & 7) * 4);
        }
    };
    auto stA2 = [&](int st, const float4* p) {
        #pragma unroll
        for (int i = 0; i < 2; i++) {
            int g = tid + i * 256;
            __half2 h0 = __floats2half2_rn(p[i].x, p[i].y);
            __half2 h1 = __floats2half2_rn(p[i].z, p[i].w);
            uint2 u;
            u.x = *reinterpret_cast<uint32_t*>(&h0);
            u.y = *reinterpret_cast<uint32_t*>(&h1);
            *reinterpret_cast<uint2*>(sm + st * A_STG + ((g >> 3) * RSH + (g & 7) * 4) * 2) = u;
        }
    };
    // B: 256 rows x 32 halves per chunk = 1024 cp16; 4 per thread
    auto loadB = [&](int st, int k0) {
        #pragma unroll
        for (int i = 0; i < 4; i++) {
            int g = tid + i * 256;
            int r = g >> 2, kq = g & 3;
            cp16(sB + st * B_STG + (r * RSH + kq * 8) * 2,
                 Wp + (size_t)r * Cn + k0 + kq * 8);
        }
    };

    float acc[2][8][4] = {};

    {   // prologue: stages 0,1,2
        float4 p[2];
        #pragma unroll
        for (int c = 0; c < 3; c++) {
            ldA2(c * 32, p);
            stA2(c, p);
            loadB(c, c * 32);
            CP_COMMIT();
        }
    }

    for (int ch = 0; ch < 8; ch++) {
        float4 pn[2];
        if (ch + 3 < 8) ldA2((ch + 3) * 32, pn);
        CP_WAIT2();
        __syncthreads();

        const int st = ch & 3;
        const uint32_t a0 = sA + st * A_STG;
        const uint32_t b0a = sB + st * B_STG;

        #pragma unroll
        for (int ks = 0; ks < 2; ks++) {
            uint32_t af[2][4];
            #pragma unroll
            for (int mt = 0; mt < 2; mt++)
                LDSM4(af[mt][0], af[mt][1], af[mt][2], af[mt][3],
                      a0 + (aoffs[mt] + ks * 16) * 2);
            uint32_t bf[8][2];
            #pragma unroll
            for (int nb = 0; nb < 4; nb++) {
                uint32_t r0, r1, r2, r3;
                LDSM4(r0, r1, r2, r3, b0a + (boffs[nb] + ks * 16) * 2);
                bf[nb * 2][0] = r0; bf[nb * 2][1] = r1;
                bf[nb * 2 + 1][0] = r2; bf[nb * 2 + 1][1] = r3;
            }
            #pragma unroll
            for (int mt = 0; mt < 2; mt++)
                #pragma unroll
                for (int nt = 0; nt < 8; nt++)
                    mma_f16(acc[mt][nt], af[mt], bf[nt]);
        }

        if (ch + 3 < 8) {
            stA2((ch + 3) & 3, pn);
            loadB((ch + 3) & 3, (ch + 3) * 32);
        }
        CP_COMMIT();
    }

    // Output
    #pragma unroll
    for (int mt = 0; mt < 2; mt++) {
        const int m = m0 + wm * 32 + mt * 16 + gid;
        #pragma unroll
        for (int nt = 0; nt < 8; nt++) {
            const int cg = wn * 64 + nt * 8 + tig * 2;
            if (OUTF32) {
                float b0 = __ldg(bias + cg), b1 = __ldg(bias + cg + 1);
                float2 v0 = make_float2(acc[mt][nt][0] + b0, acc[mt][nt][1] + b1);
                float2 v1 = make_float2(acc[mt][nt][2] + b0, acc[mt][nt][3] + b1);
                *reinterpret_cast<float2*>(Yf + (size_t)m * Cn + cg)       = v0;
                *reinterpret_cast<float2*>(Yf + (size_t)(m + 8) * Cn + cg) = v1;
            } else {
                __half2 h0 = __floats2half2_rn(acc[mt][nt][0], acc[mt][nt][1]);
                __half2 h1 = __floats2half2_rn(acc[mt][nt][2], acc[mt][nt][3]);
                *reinterpret_cast<__half2*>(Yh + (size_t)m * Cn + cg)       = h0;
                *reinterpret_cast<__half2*>(Yh + (size_t)(m + 8) * Cn + cg) = h1;
            }
        }
    }

    if (!OUTF32) {
        float cs[8][2];
        #pragma unroll
        for (int nt = 0; nt < 8; nt++) {
            cs[nt][0] = acc[0][nt][0] * acc[0][nt][0] + acc[0][nt][2] * acc[0][nt][2]
                      + acc[1][nt][0] * acc[1][nt][0] + acc[1][nt][2] * acc[1][nt][2];
            cs[nt][1] = acc[0][nt][1] * acc[0][nt][1] + acc[0][nt][3] * acc[0][nt][3]
                      + acc[1][nt][1] * acc[1][nt][1] + acc[1][nt][3] * acc[1][nt][3];
        }
        #pragma unroll
        for (int nt = 0; nt < 8; nt++)
            #pragma unroll
            for (int j = 0; j < 2; j++) {
                cs[nt][j] += __shfl_xor_sync(0xffffffffu, cs[nt][j], 4);
                cs[nt][j] += __shfl_xor_sync(0xffffffffu, cs[nt][j], 8);
                cs[nt][j] += __shfl_xor_sync(0xffffffffu, cs[nt][j], 16);
            }
        if (gid == 0) {
            #pragma unroll
            for (int nt = 0; nt < 8; nt++) {
                part[wm * 256 + wn * 64 + nt * 8 + tig * 2]     = cs[nt][0];
                part[wm * 256 + wn * 64 + nt * 8 + tig * 2 + 1] = cs[nt][1];
            }
        }
        __syncthreads();
        {
            float s = part[tid] + part[256 + tid];
            nssp[((size_t)z * NCTAQ + blockIdx.x) * 256 + tid] = s;
        }
    }
}

// ---------------------------------------------------------------------------
// Reduce per-CTA sumsq partials -> per-batch norms (deterministic order)
// ---------------------------------------------------------------------------
__global__ void __launch_bounds__(256) reduce_nss(const float* __restrict__ nssp,
                                                  float* __restrict__ nss2)
{
    const int b = blockIdx.x, z = blockIdx.y, c = threadIdx.x;
    float s = 0.f;
    #pragma unroll 8
    for (int i = 0; i < NCTAQ / Bn; i++)
        s += nssp[((size_t)z * NCTAQ + b * (NCTAQ / Bn) + i) * 256 + c];
    nss2[(z * Bn + b) * 256 + c] = s;
}

// ---------------------------------------------------------------------------
// Gram via fp16 mma with ldmatrix.trans — 4-stage cp.async, single barrier
// ---------------------------------------------------------------------------
#define GRS 72
#define GSTG (64*GRS*2)          // 9216 B per operand per stage
#define GSMEM (8*GSTG)           // 73728 B

__global__ void __launch_bounds__(256) gram_mma(const __half* __restrict__ Qh,
                                                const __half* __restrict__ Kh,
                                                float* __restrict__ Gp)
{
    extern __shared__ char smg[];
    const uint32_t sq = smem_u32(smg);
    const uint32_t sk = sq + 4 * GSTG;

    const int bh = blockIdx.x, sp = blockIdx.y;
    const int b = bh >> 2, h = bh & 3;
    const int tid = threadIdx.x;
    const int w = tid >> 5, lane = tid & 31;
    const int gid = lane >> 2, tig = lane & 3;
    const int t0 = sp * GSL;

    const __half* qb = Qh + ((size_t)b * Nn) * 256 + h * 64;
    const __half* kb = Kh + ((size_t)b * Nn) * 256 + h * 64;

    auto gload = [&](int st, int tc) {
        #pragma unroll
        for (int i = 0; i < 2; i++) {
            int g = tid + i * 256;
            int r = g >> 3, ck = g & 7;
            cp16(sq + st * GSTG + (r * GRS + ck * 8) * 2,
                 qb + (size_t)(t0 + tc + r) * 256 + ck * 8);
        }
        #pragma unroll
        for (int i = 0; i < 2; i++) {
            int g = tid + i * 256;
            int r = g >> 3, ck = g & 7;
            cp16(sk + st * GSTG + (r * GRS + ck * 8) * 2,
                 kb + (size_t)(t0 + tc + r) * 256 + ck * 8);
        }
    };

    const int aH = (((lane >> 4) & 1) * 8 + (lane & 7)) * GRS + ((lane >> 3) & 1) * 8;
    const int bH = (((lane >> 3) & 1) * 8 + (lane & 7)) * GRS + w * 8;

    float acc[4][4] = {};

    gload(0, 0);   CP_COMMIT();
    gload(1, 64);  CP_COMMIT();
    gload(2, 128); CP_COMMIT();

    const int NCH = GSL / 64;   // 16
    for (int c = 0; c < NCH; c++) {
        CP_WAIT2();
        __syncthreads();
        if (c + 3 < NCH) gload((c + 3) & 3, (c + 3) * 64);
        CP_COMMIT();

        const uint32_t aq = sq + (c & 3) * GSTG;
        const uint32_t ak = sk + (c & 3) * GSTG;

        #pragma unroll
        for (int st16 = 0; st16 < 4; st16++) {
            const int kb16 = st16 * 16;
            uint32_t bfr[2];
            LDSM2T(bfr[0], bfr[1], ak + (kb16 * GRS + bH) * 2);
            #pragma unroll
            for (int mt = 0; mt < 4; mt++) {
                uint32_t af[4];
                LDSM4T(af[0], af[1], af[2], af[3],
                       aq + (kb16 * GRS + aH + mt * 16) * 2);
                mma_f16(acc[mt], af, bfr);
            }
        }
    }

    float* g = Gp + (((size_t)bh * GSP + sp) << 12);
    #pragma unroll
    for (int mt = 0; mt < 4; mt++) {
        const int r0 = mt * 16 + gid;
        *reinterpret_cast<float2*>(g + r0 * 64 + w * 8 + tig * 2) =
            make_float2(acc[mt][0], acc[mt][1]);
        *reinterpret_cast<float2*>(g + (r0 + 8) * 64 + w * 8 + tig * 2) =
            make_float2(acc[mt][2], acc[mt][3]);
    }
}

// ---------------------------------------------------------------------------
// Weight f32 -> f16
// ---------------------------------------------------------------------------
__device__ __forceinline__ void cvt_store4(__half* dst, float4 v) {
    __half2 h0 = __floats2half2_rn(v.x, v.y);
    __half2 h1 = __floats2half2_rn(v.z, v.w);
    uint2 u;
    u.x = *reinterpret_cast<uint32_t*>(&h0);
    u.y = *reinterpret_cast<uint32_t*>(&h1);
    *reinterpret_cast<uint2*>(dst) = u;
}

__global__ void __launch_bounds__(256) cvt_w_kernel(const float4* __restrict__ wq,
                                                    const float4* __restrict__ wk,
                                                    __half* dst)
{
    const int n4 = (Cn * Cn) / 4;
    const float4* src = blockIdx.y == 0 ? wq : wk;
    __half* d = dst + (size_t)blockIdx.y * Cn * Cn;
    int i = blockIdx.x * 256 + threadIdx.x;
    if (i < n4) cvt_store4(d + i * 4, src[i]);
}

// ---------------------------------------------------------------------------
// Reduce gram partials, normalize * temperature, softmax
// ---------------------------------------------------------------------------
__global__ void __launch_bounds__(64) softmax_kernel(const float* __restrict__ Gp,
                                                     const float* __restrict__ nss2,
                                                     const float* __restrict__ temp,
                                                     float* __restrict__ A)
{
    const int r  = blockIdx.x;
    const int bh = r >> 6;
    const int dd = r & 63;
    const int b  = bh >> 2, h = bh & 3;
    const int e  = threadIdx.x;

    const float rq = 1.0f / fmaxf(sqrtf(nss2[(0 * Bn + b) * 256 + h * 64 + dd]), 1e-12f);
    const float rk = 1.0f / fmaxf(sqrtf(nss2[(1 * Bn + b) * 256 + h * 64 + e]), 1e-12f);

    float s = 0.f;
    #pragma unroll
    for (int sp = 0; sp < GSP; sp++)
        s += Gp[(((size_t)bh * GSP + sp) << 12) + dd * 64 + e];
    s *= rq * rk * temp[h];

    __shared__ float red[64];
    red[e] = s;
    __syncthreads();
    for (int st = 32; st > 0; st >>= 1) {
        if (e < st) red[e] = fmaxf(red[e], red[e + st]);
        __syncthreads();
    }
    float m = red[0];
    __syncthreads();
    float ex = __expf(s - m);
    red[e] = ex;
    __syncthreads();
    for (int st = 32; st > 0; st >>= 1) {
        if (e < st) red[e] += red[e + st];
        __syncthreads();
    }
    A[(size_t)bh * 4096 + dd * 64 + e] = ex / red[0];
}

// ---------------------------------------------------------------------------
// fold1: U_b[h*64+dd][k] = sum_e attn[bh][dd][e] * Wv[h*64+e][k]   (fp32)
// ---------------------------------------------------------------------------
__global__ void __launch_bounds__(256) fold1_kernel(const float* __restrict__ A,
                                                    const float* __restrict__ Wv,
                                                    float* __restrict__ U)
{
    __shared__ float at[64][65];
    __shared__ float wv[64][65];
    const int bh = blockIdx.x, kq = blockIdx.y;
    const int b = bh >> 2, h = bh & 3;
    const int tx = threadIdx.x & 15, ty = threadIdx.x >> 4;
    const int tid = threadIdx.x;

    const float* Ab = A + (size_t)bh * 4096;
    #pragma unroll
    for (int i = 0; i < 16; i++) {
        int idx = tid + i * 256;
        at[idx >> 6][idx & 63] = Ab[idx];
    }
    #pragma unroll
    for (int i = 0; i < 16; i++) {
        int idx = tid + i * 256;
        wv[idx >> 6][idx & 63] = Wv[(size_t)(h * 64 + (idx >> 6)) * 256 + kq * 64 + (idx & 63)];
    }
    __syncthreads();

    float acc[4][4] = {};
    #pragma unroll
    for (int e = 0; e < 64; e++) {
        float av[4], bv[4];
        #pragma unroll
        for (int i = 0; i < 4; i++) av[i] = at[ty * 4 + i][e];
        #pragma unroll
        for (int j = 0; j < 4; j++) bv[j] = wv[e][tx * 4 + j];
        #pragma unroll
        for (int i = 0; i < 4; i++)
            #pragma unroll
            for (int j = 0; j < 4; j++)
                acc[i][j] += av[i] * bv[j];
    }
    #pragma unroll
    for (int i = 0; i < 4; i++)
        #pragma unroll
        for (int j = 0; j < 4; j++)
            U[((size_t)b * 256 + h * 64 + ty * 4 + i) * 256 + kq * 64 + tx * 4 + j] = acc[i][j];
}

// ---------------------------------------------------------------------------
// fold2: W2_b[c][k] = sum_ddg Wo[c][ddg] * U_b[ddg][k]   -> fp16
// ---------------------------------------------------------------------------
__global__ void __launch_bounds__(256) fold2_kernel(const float* __restrict__ Wo,
                                                    const float* __restrict__ U,
                                                    __half* __restrict__ W2)
{
    __shared__ float ws[16][68];
    __shared__ float us[16][68];
    const int cq = blockIdx.x, kq = blockIdx.y, b = blockIdx.z;
    const int tid = threadIdx.x;
    const int tx = tid & 15, ty = tid >> 4;
    const int lrow = tid >> 2, lk4 = (tid & 3) * 4;
    const int krow = tid >> 4, kc4 = (tid & 15) * 4;

    const float* Ub = U + ((size_t)b << 16);
    float acc[4][4] = {};

    for (int k0 = 0; k0 < 256; k0 += 16) {
        float4 wv4 = *reinterpret_cast<const float4*>(
            Wo + (size_t)(cq * 64 + lrow) * 256 + k0 + lk4);
        float4 uv4 = *reinterpret_cast<const float4*>(
            Ub + (size_t)(k0 + krow) * 256 + kq * 64 + kc4);
        __syncthreads();
        ws[lk4+0][lrow] = wv4.x; ws[lk4+1][lrow] = wv4.y;
        ws[lk4+2][lrow] = wv4.z; ws[lk4+3][lrow] = wv4.w;
        *reinterpret_cast<float4*>(&us[krow][kc4]) = uv4;
        __syncthreads();
        #pragma unroll
        for (int kk = 0; kk < 16; kk++) {
            float4 a = *reinterpret_cast<const float4*>(&ws[kk][ty * 4]);
            float4 bb = *reinterpret_cast<const float4*>(&us[kk][tx * 4]);
            float av[4] = {a.x, a.y, a.z, a.w};
            float bv[4] = {bb.x, bb.y, bb.z, bb.w};
            #pragma unroll
            for (int i = 0; i < 4; i++)
                #pragma unroll
                for (int j = 0; j < 4; j++)
                    acc[i][j] += av[i] * bv[j];
        }
    }
    #pragma unroll
    for (int i = 0; i < 4; i++)
        #pragma unroll
        for (int j = 0; j < 4; j++)
            W2[((size_t)b << 16) + (size_t)(cq * 64 + ty * 4 + i) * 256 + kq * 64 + tx * 4 + j] =
                __float2half(acc[i][j]);
}

// ---------------------------------------------------------------------------
extern "C" void kernel_launch(void* const* d_in, const int* in_sizes, int n_in,
                              void* d_out, int out_size)
{
    (void)in_sizes; (void)n_in; (void)out_size;
    const float* x1 = (const float*)d_in[0];
    const float* x2 = (const float*)d_in[1];
    const float* Wq = (const float*)d_in[2];
    const float* Wk = (const float*)d_in[3];
    const float* Wv = (const float*)d_in[4];
    const float* Wo = (const float*)d_in[5];
    const float* bo = (const float*)d_in[6];
    const float* temperature = (const float*)d_in[7];
    float* out = (float*)d_out;

    __half *qh, *kh, *wh, *w2h;
    float *u, *gp, *attn, *nssp, *nss2;
    cudaGetSymbolAddress((void**)&qh,  g_qh);
    cudaGetSymbolAddress((void**)&kh,  g_kh);
    cudaGetSymbolAddress((void**)&wh,  g_wh);
    cudaGetSymbolAddress((void**)&w2h, g_w2h);
    cudaGetSymbolAddress((void**)&u,   g_u);
    cudaGetSymbolAddress((void**)&gp,  g_gp);
    cudaGetSymbolAddress((void**)&attn, g_attn);
    cudaGetSymbolAddress((void**)&nssp, g_nssp);
    cudaGetSymbolAddress((void**)&nss2, g_nss2);

    cudaFuncSetAttribute(gemm_h<false>, cudaFuncAttributeMaxDynamicSharedMemorySize, SMEM_T);
    cudaFuncSetAttribute(gemm_h<true >, cudaFuncAttributeMaxDynamicSharedMemorySize, SMEM_T);
    cudaFuncSetAttribute(gram_mma, cudaFuncAttributeMaxDynamicSharedMemorySize, GSMEM);

    cvt_w_kernel<<<dim3(64, 2), 256>>>((const float4*)Wq, (const float4*)Wk, wh);

    gemm_h<false><<<dim3(NCTAQ, 1, 2), 256, SMEM_T>>>(
        x1, wh, qh, x2, wh + Cn * Cn, kh, nullptr, nullptr, nssp);

    reduce_nss<<<dim3(Bn, 2), 256>>>(nssp, nss2);
    gram_mma<<<dim3(BHn, GSP), 256, GSMEM>>>(qh, kh, gp);
    softmax_kernel<<<BHn * Dn, 64>>>(gp, nss2, temperature, attn);

    fold1_kernel<<<dim3(BHn, 4), 256>>>(attn, Wv, u);
    fold2_kernel<<<dim3(4, 4, Bn), 256>>>(Wo, u, w2h);

    gemm_h<true><<<dim3(NCTAQ, 1, 1), 256, SMEM_T>>>(
        x2, w2h, nullptr, nullptr, nullptr, nullptr, bo, out, nullptr);
}

// round 15
// speedup vs baseline: 1.0688x; 1.0688x over previous
#include <cuda_runtime.h>
#include <cuda_fp16.h>
#include <math.h>
#include <stdint.h>

#define Bn 8
#define Nn 8192
#define Cn 256
#define Hn 4
#define Dn 64
#define BHn (Bn*Hn)
#define MTOT (Bn*Nn)
#define GSP 8
#define GSL (Nn/GSP)      // 1024
#define NCTA (MTOT/128)   // 512

// ---------------------------------------------------------------------------
// Scratch (__device__ globals; no allocation allowed)
// ---------------------------------------------------------------------------
__device__ __half g_qh [MTOT*Cn];
__device__ __half g_kh [MTOT*Cn];
__device__ __half g_wh [2*Cn*Cn];
__device__ __half g_w2h[Bn*Cn*Cn];
__device__ float  g_u  [Bn*Cn*Cn];
__device__ float  g_gp [BHn*GSP*Dn*Dn];
__device__ float  g_attn[BHn*Dn*Dn];
__device__ float  g_nssp[2*NCTA*Cn];
__device__ float  g_nss2[2*Bn*Cn];

// ---------------------------------------------------------------------------
// Helpers
// ---------------------------------------------------------------------------
__device__ __forceinline__ uint32_t smem_u32(const void* p) {
    uint32_t a;
    asm("{ .reg .u64 t; cvta.to.shared.u64 t, %1; cvt.u32.u64 %0, t; }" : "=r"(a) : "l"(p));
    return a;
}
__device__ __forceinline__ void cp16(uint32_t sdst, const void* gsrc) {
    asm volatile("cp.async.cg.shared.global [%0], [%1], 16;"
                 :: "r"(sdst), "l"(__cvta_generic_to_global(gsrc)) : "memory");
}
#define CP_COMMIT() asm volatile("cp.async.commit_group;" ::: "memory")
#define CP_WAIT2()  asm volatile("cp.async.wait_group 2;" ::: "memory")

#define LDSM4(r0, r1, r2, r3, addr) \
    asm volatile("ldmatrix.sync.aligned.m8n8.x4.shared.b16 {%0,%1,%2,%3}, [%4];" \
                 : "=r"(r0), "=r"(r1), "=r"(r2), "=r"(r3) : "r"(addr))
#define LDSM4T(r0, r1, r2, r3, addr) \
    asm volatile("ldmatrix.sync.aligned.m8n8.x4.trans.shared.b16 {%0,%1,%2,%3}, [%4];" \
                 : "=r"(r0), "=r"(r1), "=r"(r2), "=r"(r3) : "r"(addr))
#define LDSM2T(r0, r1, addr) \
    asm volatile("ldmatrix.sync.aligned.m8n8.x2.trans.shared.b16 {%0,%1}, [%2];" \
                 : "=r"(r0), "=r"(r1) : "r"(addr))

__device__ __forceinline__ void mma_f16(float* d, const uint32_t* a, const uint32_t* b) {
    asm volatile(
        "mma.sync.aligned.m16n8k16.row.col.f32.f16.f16.f32 "
        "{%0,%1,%2,%3}, {%4,%5,%6,%7}, {%8,%9}, {%0,%1,%2,%3};"
        : "+f"(d[0]), "+f"(d[1]), "+f"(d[2]), "+f"(d[3])
        : "r"(a[0]), "r"(a[1]), "r"(a[2]), "r"(a[3]), "r"(b[0]), "r"(b[1]));
}

// ---------------------------------------------------------------------------
// fp16 mma GEMM, fp32 A converted in-flight, CTA 128x256, 512 threads,
// warps 4Mx4N (32x64 each). K=256 in 4 chunks of 64, 4-stage pipeline
// (prologue fills 3 chunks; wait_group 2 keeps 3 chunks in flight).
// Round-9 ordering: MMA block first, then stA4 + loadB + commit.
// ---------------------------------------------------------------------------
#define RSH 72
#define A_STG (128*RSH*2)               // 18432 B
#define B_STG (256*RSH*2)               // 36864 B
#define NST 4
#define SMEM_T (NST*(A_STG+B_STG) + 4096)  // 225280 B

template<bool OUTF32>
__global__ void __launch_bounds__(512, 1) gemm_h(const float* __restrict__ X0,
                                                 const __half* __restrict__ W0,
                                                 __half* __restrict__ Yh0,
                                                 const float* __restrict__ X1,
                                                 const __half* __restrict__ W1,
                                                 __half* __restrict__ Yh1,
                                                 const float* __restrict__ bias,
                                                 float* __restrict__ Yf,
                                                 float* __restrict__ nssp)
{
    extern __shared__ char sm[];
    const uint32_t sA = smem_u32(sm);
    const uint32_t sB = sA + NST * A_STG;
    float* part = reinterpret_cast<float*>(sm + NST * (A_STG + B_STG));

    const int tid  = threadIdx.x;
    const int wid  = tid >> 5, lane = tid & 31;
    const int wm   = wid & 3;
    const int wn   = wid >> 2;
    const int gid  = lane >> 2;
    const int tig  = lane & 3;
    const int m0   = blockIdx.x * 128;
    const int z    = OUTF32 ? 0 : blockIdx.z;

    const float* X = (!OUTF32 && z) ? X1 : X0;
    const __half* Wp = OUTF32 ? W0 + ((size_t)(m0 >> 13) << 16) : (z ? W1 : W0);
    __half* Yh = z ? Yh1 : Yh0;

    const int lrA = ((lane >> 3) & 1) * 8 + (lane & 7);
    const int lkA = (lane >> 4) * 8;
    const int lrB = (lane >> 4) * 8 + (lane & 7);
    const int lkB = ((lane >> 3) & 1) * 8;
    int aoffs[2], boffs[4];
    #pragma unroll
    for (int mt = 0; mt < 2; mt++) aoffs[mt] = (wm * 32 + mt * 16 + lrA) * RSH + lkA;
    #pragma unroll
    for (int nb = 0; nb < 4; nb++) boffs[nb] = (wn * 64 + nb * 16 + lrB) * RSH + lkB;

    auto ldA4 = [&](int k0, float4* p) {
        #pragma unroll
        for (int i = 0; i < 4; i++) {
            int g = tid + i * 512;
            p[i] = *reinterpret_cast<const float4*>(
                X + (size_t)(m0 + (g >> 4)) * Cn + k0 + (g & 15) * 4);
        }
    };
    auto stA4 = [&](int st, const float4* p) {
        #pragma unroll
        for (int i = 0; i < 4; i++) {
            int g = tid + i * 512;
            __half2 h0 = __floats2half2_rn(p[i].x, p[i].y);
            __half2 h1 = __floats2half2_rn(p[i].z, p[i].w);
            uint2 u;
            u.x = *reinterpret_cast<uint32_t*>(&h0);
            u.y = *reinterpret_cast<uint32_t*>(&h1);
            *reinterpret_cast<uint2*>(sm + st * A_STG + ((g >> 4) * RSH + (g & 15) * 4) * 2) = u;
        }
    };
    auto loadB = [&](int st, int k0) {
        #pragma unroll
        for (int i = 0; i < 4; i++) {
            int g = tid + i * 512;
            int r = g >> 3, kq = g & 7;
            cp16(sB + st * B_STG + (r * RSH + kq * 8) * 2,
                 Wp + (size_t)r * Cn + k0 + kq * 8);
        }
    };

    float acc[2][8][4] = {};

    {   // prologue: stages 0,1,2
        float4 p[4];
        #pragma unroll
        for (int c = 0; c < 3; c++) {
            ldA4(c * 64, p);
            stA4(c, p);
            loadB(c, c * 64);
            CP_COMMIT();
        }
    }

    for (int ch = 0; ch < 4; ch++) {
        float4 pn[4];
        if (ch + 3 < 4) ldA4((ch + 3) * 64, pn);
        CP_WAIT2();
        __syncthreads();

        const int st = ch & 3;
        const uint32_t a0 = sA + st * A_STG;
        const uint32_t b0a = sB + st * B_STG;

        #pragma unroll
        for (int ks = 0; ks < 4; ks++) {
            uint32_t af[2][4];
            #pragma unroll
            for (int mt = 0; mt < 2; mt++)
                LDSM4(af[mt][0], af[mt][1], af[mt][2], af[mt][3],
                      a0 + (aoffs[mt] + ks * 16) * 2);
            uint32_t bf[8][2];
            #pragma unroll
            for (int nb = 0; nb < 4; nb++) {
                uint32_t r0, r1, r2, r3;
                LDSM4(r0, r1, r2, r3, b0a + (boffs[nb] + ks * 16) * 2);
                bf[nb * 2][0] = r0; bf[nb * 2][1] = r1;
                bf[nb * 2 + 1][0] = r2; bf[nb * 2 + 1][1] = r3;
            }
            #pragma unroll
            for (int mt = 0; mt < 2; mt++)
                #pragma unroll
                for (int nt = 0; nt < 8; nt++)
                    mma_f16(acc[mt][nt], af[mt], bf[nt]);
        }

        if (ch + 3 < 4) {
            stA4((ch + 3) & 3, pn);
            loadB((ch + 3) & 3, (ch + 3) * 64);
        }
        CP_COMMIT();
    }

    // Output
    #pragma unroll
    for (int mt = 0; mt < 2; mt++) {
        const int m = m0 + wm * 32 + mt * 16 + gid;
        #pragma unroll
        for (int nt = 0; nt < 8; nt++) {
            const int cg = wn * 64 + nt * 8 + tig * 2;
            if (OUTF32) {
                float b0 = __ldg(bias + cg), b1 = __ldg(bias + cg + 1);
                float2 v0 = make_float2(acc[mt][nt][0] + b0, acc[mt][nt][1] + b1);
                float2 v1 = make_float2(acc[mt][nt][2] + b0, acc[mt][nt][3] + b1);
                *reinterpret_cast<float2*>(Yf + (size_t)m * Cn + cg)       = v0;
                *reinterpret_cast<float2*>(Yf + (size_t)(m + 8) * Cn + cg) = v1;
            } else {
                __half2 h0 = __floats2half2_rn(acc[mt][nt][0], acc[mt][nt][1]);
                __half2 h1 = __floats2half2_rn(acc[mt][nt][2], acc[mt][nt][3]);
                *reinterpret_cast<__half2*>(Yh + (size_t)m * Cn + cg)       = h0;
                *reinterpret_cast<__half2*>(Yh + (size_t)(m + 8) * Cn + cg) = h1;
            }
        }
    }

    if (!OUTF32) {
        float cs[8][2];
        #pragma unroll
        for (int nt = 0; nt < 8; nt++) {
            cs[nt][0] = acc[0][nt][0] * acc[0][nt][0] + acc[0][nt][2] * acc[0][nt][2]
                      + acc[1][nt][0] * acc[1][nt][0] + acc[1][nt][2] * acc[1][nt][2];
            cs[nt][1] = acc[0][nt][1] * acc[0][nt][1] + acc[0][nt][3] * acc[0][nt][3]
                      + acc[1][nt][1] * acc[1][nt][1] + acc[1][nt][3] * acc[1][nt][3];
        }
        #pragma unroll
        for (int nt = 0; nt < 8; nt++)
            #pragma unroll
            for (int j = 0; j < 2; j++) {
                cs[nt][j] += __shfl_xor_sync(0xffffffffu, cs[nt][j], 4);
                cs[nt][j] += __shfl_xor_sync(0xffffffffu, cs[nt][j], 8);
                cs[nt][j] += __shfl_xor_sync(0xffffffffu, cs[nt][j], 16);
            }
        if (gid == 0) {
            #pragma unroll
            for (int nt = 0; nt < 8; nt++) {
                part[wm * 256 + wn * 64 + nt * 8 + tig * 2]     = cs[nt][0];
                part[wm * 256 + wn * 64 + nt * 8 + tig * 2 + 1] = cs[nt][1];
            }
        }
        __syncthreads();
        if (tid < 256) {
            float s = part[tid] + part[256 + tid] + part[512 + tid] + part[768 + tid];
            nssp[((size_t)z * NCTA + blockIdx.x) * 256 + tid] = s;
        }
    }
}

// ---------------------------------------------------------------------------
// Reduce per-CTA sumsq partials -> per-batch norms (deterministic order)
// ---------------------------------------------------------------------------
__global__ void __launch_bounds__(256) reduce_nss(const float* __restrict__ nssp,
                                                  float* __restrict__ nss2)
{
    const int b = blockIdx.x, z = blockIdx.y, c = threadIdx.x;
    float s = 0.f;
    #pragma unroll 8
    for (int i = 0; i < 64; i++)
        s += nssp[((size_t)z * NCTA + b * 64 + i) * 256 + c];
    nss2[(z * Bn + b) * 256 + c] = s;
}

// ---------------------------------------------------------------------------
// Gram via fp16 mma with ldmatrix.trans — 4-stage cp.async, single barrier
// ---------------------------------------------------------------------------
#define GRS 72
#define GSTG (64*GRS*2)          // 9216 B per operand per stage
#define GSMEM (8*GSTG)           // 73728 B

__global__ void __launch_bounds__(256) gram_mma(const __half* __restrict__ Qh,
                                                const __half* __restrict__ Kh,
                                                float* __restrict__ Gp)
{
    extern __shared__ char smg[];
    const uint32_t sq = smem_u32(smg);
    const uint32_t sk = sq + 4 * GSTG;

    const int bh = blockIdx.x, sp = blockIdx.y;
    const int b = bh >> 2, h = bh & 3;
    const int tid = threadIdx.x;
    const int w = tid >> 5, lane = tid & 31;
    const int gid = lane >> 2, tig = lane & 3;
    const int t0 = sp * GSL;

    const __half* qb = Qh + ((size_t)b * Nn) * 256 + h * 64;
    const __half* kb = Kh + ((size_t)b * Nn) * 256 + h * 64;

    auto gload = [&](int st, int tc) {
        #pragma unroll
        for (int i = 0; i < 2; i++) {
            int g = tid + i * 256;
            int r = g >> 3, ck = g & 7;
            cp16(sq + st * GSTG + (r * GRS + ck * 8) * 2,
                 qb + (size_t)(t0 + tc + r) * 256 + ck * 8);
        }
        #pragma unroll
        for (int i = 0; i < 2; i++) {
            int g = tid + i * 256;
            int r = g >> 3, ck = g & 7;
            cp16(sk + st * GSTG + (r * GRS + ck * 8) * 2,
                 kb + (size_t)(t0 + tc + r) * 256 + ck * 8);
        }
    };

    const int aH = (((lane >> 4) & 1) * 8 + (lane & 7)) * GRS + ((lane >> 3) & 1) * 8;
    const int bH = (((lane >> 3) & 1) * 8 + (lane & 7)) * GRS + w * 8;

    float acc[4][4] = {};

    gload(0, 0);   CP_COMMIT();
    gload(1, 64);  CP_COMMIT();
    gload(2, 128); CP_COMMIT();

    const int NCH = GSL / 64;   // 16
    for (int c = 0; c < NCH; c++) {
        CP_WAIT2();
        __syncthreads();
        if (c + 3 < NCH) gload((c + 3) & 3, (c + 3) * 64);
        CP_COMMIT();

        const uint32_t aq = sq + (c & 3) * GSTG;
        const uint32_t ak = sk + (c & 3) * GSTG;

        #pragma unroll
        for (int st16 = 0; st16 < 4; st16++) {
            const int kb16 = st16 * 16;
            uint32_t bfr[2];
            LDSM2T(bfr[0], bfr[1], ak + (kb16 * GRS + bH) * 2);
            #pragma unroll
            for (int mt = 0; mt < 4; mt++) {
                uint32_t af[4];
                LDSM4T(af[0], af[1], af[2], af[3],
                       aq + (kb16 * GRS + aH + mt * 16) * 2);
                mma_f16(acc[mt], af, bfr);
            }
        }
    }

    float* g = Gp + (((size_t)bh * GSP + sp) << 12);
    #pragma unroll
    for (int mt = 0; mt < 4; mt++) {
        const int r0 = mt * 16 + gid;
        *reinterpret_cast<float2*>(g + r0 * 64 + w * 8 + tig * 2) =
            make_float2(acc[mt][0], acc[mt][1]);
        *reinterpret_cast<float2*>(g + (r0 + 8) * 64 + w * 8 + tig * 2) =
            make_float2(acc[mt][2], acc[mt][3]);
    }
}

// ---------------------------------------------------------------------------
// Weight f32 -> f16
// ---------------------------------------------------------------------------
__device__ __forceinline__ void cvt_store4(__half* dst, float4 v) {
    __half2 h0 = __floats2half2_rn(v.x, v.y);
    __half2 h1 = __floats2half2_rn(v.z, v.w);
    uint2 u;
    u.x = *reinterpret_cast<uint32_t*>(&h0);
    u.y = *reinterpret_cast<uint32_t*>(&h1);
    *reinterpret_cast<uint2*>(dst) = u;
}

__global__ void __launch_bounds__(256) cvt_w_kernel(const float4* __restrict__ wq,
                                                    const float4* __restrict__ wk,
                                                    __half* dst)
{
    const int n4 = (Cn * Cn) / 4;
    const float4* src = blockIdx.y == 0 ? wq : wk;
    __half* d = dst + (size_t)blockIdx.y * Cn * Cn;
    int i = blockIdx.x * 256 + threadIdx.x;
    if (i < n4) cvt_store4(d + i * 4, src[i]);
}

// ---------------------------------------------------------------------------
// Reduce gram partials, normalize * temperature, softmax
// ---------------------------------------------------------------------------
__global__ void __launch_bounds__(64) softmax_kernel(const float* __restrict__ Gp,
                                                     const float* __restrict__ nss2,
                                                     const float* __restrict__ temp,
                                                     float* __restrict__ A)
{
    const int r  = blockIdx.x;
    const int bh = r >> 6;
    const int dd = r & 63;
    const int b  = bh >> 2, h = bh & 3;
    const int e  = threadIdx.x;

    const float rq = 1.0f / fmaxf(sqrtf(nss2[(0 * Bn + b) * 256 + h * 64 + dd]), 1e-12f);
    const float rk = 1.0f / fmaxf(sqrtf(nss2[(1 * Bn + b) * 256 + h * 64 + e]), 1e-12f);

    float s = 0.f;
    #pragma unroll
    for (int sp = 0; sp < GSP; sp++)
        s += Gp[(((size_t)bh * GSP + sp) << 12) + dd * 64 + e];
    s *= rq * rk * temp[h];

    __shared__ float red[64];
    red[e] = s;
    __syncthreads();
    for (int st = 32; st > 0; st >>= 1) {
        if (e < st) red[e] = fmaxf(red[e], red[e + st]);
        __syncthreads();
    }
    float m = red[0];
    __syncthreads();
    float ex = __expf(s - m);
    red[e] = ex;
    __syncthreads();
    for (int st = 32; st > 0; st >>= 1) {
        if (e < st) red[e] += red[e + st];
        __syncthreads();
    }
    A[(size_t)bh * 4096 + dd * 64 + e] = ex / red[0];
}

// ---------------------------------------------------------------------------
// fold1: U_b[h*64+dd][k] = sum_e attn[bh][dd][e] * Wv[h*64+e][k]   (fp32)
// ---------------------------------------------------------------------------
__global__ void __launch_bounds__(256) fold1_kernel(const float* __restrict__ A,
                                                    const float* __restrict__ Wv,
                                                    float* __restrict__ U)
{
    __shared__ float at[64][65];
    __shared__ float wv[64][65];
    const int bh = blockIdx.x, kq = blockIdx.y;
    const int b = bh >> 2, h = bh & 3;
    const int tx = threadIdx.x & 15, ty = threadIdx.x >> 4;
    const int tid = threadIdx.x;

    const float* Ab = A + (size_t)bh * 4096;
    #pragma unroll
    for (int i = 0; i < 16; i++) {
        int idx = tid + i * 256;
        at[idx >> 6][idx & 63] = Ab[idx];
    }
    #pragma unroll
    for (int i = 0; i < 16; i++) {
        int idx = tid + i * 256;
        wv[idx >> 6][idx & 63] = Wv[(size_t)(h * 64 + (idx >> 6)) * 256 + kq * 64 + (idx & 63)];
    }
    __syncthreads();

    float acc[4][4] = {};
    #pragma unroll
    for (int e = 0; e < 64; e++) {
        float av[4], bv[4];
        #pragma unroll
        for (int i = 0; i < 4; i++) av[i] = at[ty * 4 + i][e];
        #pragma unroll
        for (int j = 0; j < 4; j++) bv[j] = wv[e][tx * 4 + j];
        #pragma unroll
        for (int i = 0; i < 4; i++)
            #pragma unroll
            for (int j = 0; j < 4; j++)
                acc[i][j] += av[i] * bv[j];
    }
    #pragma unroll
    for (int i = 0; i < 4; i++)
        #pragma unroll
        for (int j = 0; j < 4; j++)
            U[((size_t)b * 256 + h * 64 + ty * 4 + i) * 256 + kq * 64 + tx * 4 + j] = acc[i][j];
}

// ---------------------------------------------------------------------------
// fold2: W2_b[c][k] = sum_ddg Wo[c][ddg] * U_b[ddg][k]   -> fp16
// ---------------------------------------------------------------------------
__global__ void __launch_bounds__(256) fold2_kernel(const float* __restrict__ Wo,
                                                    const float* __restrict__ U,
                                                    __half* __restrict__ W2)
{
    __shared__ float ws[16][68];
    __shared__ float us[16][68];
    const int cq = blockIdx.x, kq = blockIdx.y, b = blockIdx.z;
    const int tid = threadIdx.x;
    const int tx = tid & 15, ty = tid >> 4;
    const int lrow = tid >> 2, lk4 = (tid & 3) * 4;
    const int krow = tid >> 4, kc4 = (tid & 15) * 4;

    const float* Ub = U + ((size_t)b << 16);
    float acc[4][4] = {};

    for (int k0 = 0; k0 < 256; k0 += 16) {
        float4 wv4 = *reinterpret_cast<const float4*>(
            Wo + (size_t)(cq * 64 + lrow) * 256 + k0 + lk4);
        float4 uv4 = *reinterpret_cast<const float4*>(
            Ub + (size_t)(k0 + krow) * 256 + kq * 64 + kc4);
        __syncthreads();
        ws[lk4+0][lrow] = wv4.x; ws[lk4+1][lrow] = wv4.y;
        ws[lk4+2][lrow] = wv4.z; ws[lk4+3][lrow] = wv4.w;
        *reinterpret_cast<float4*>(&us[krow][kc4]) = uv4;
        __syncthreads();
        #pragma unroll
        for (int kk = 0; kk < 16; kk++) {
            float4 a = *reinterpret_cast<const float4*>(&ws[kk][ty * 4]);
            float4 bb = *reinterpret_cast<const float4*>(&us[kk][tx * 4]);
            float av[4] = {a.x, a.y, a.z, a.w};
            float bv[4] = {bb.x, bb.y, bb.z, bb.w};
            #pragma unroll
            for (int i = 0; i < 4; i++)
                #pragma unroll
                for (int j = 0; j < 4; j++)
                    acc[i][j] += av[i] * bv[j];
        }
    }
    #pragma unroll
    for (int i = 0; i < 4; i++)
        #pragma unroll
        for (int j = 0; j < 4; j++)
            W2[((size_t)b << 16) + (size_t)(cq * 64 + ty * 4 + i) * 256 + kq * 64 + tx * 4 + j] =
                __float2half(acc[i][j]);
}

// ---------------------------------------------------------------------------
extern "C" void kernel_launch(void* const* d_in, const int* in_sizes, int n_in,
                              void* d_out, int out_size)
{
    (void)in_sizes; (void)n_in; (void)out_size;
    const float* x1 = (const float*)d_in[0];
    const float* x2 = (const float*)d_in[1];
    const float* Wq = (const float*)d_in[2];
    const float* Wk = (const float*)d_in[3];
    const float* Wv = (const float*)d_in[4];
    const float* Wo = (const float*)d_in[5];
    const float* bo = (const float*)d_in[6];
    const float* temperature = (const float*)d_in[7];
    float* out = (float*)d_out;

    __half *qh, *kh, *wh, *w2h;
    float *u, *gp, *attn, *nssp, *nss2;
    cudaGetSymbolAddress((void**)&qh,  g_qh);
    cudaGetSymbolAddress((void**)&kh,  g_kh);
    cudaGetSymbolAddress((void**)&wh,  g_wh);
    cudaGetSymbolAddress((void**)&w2h, g_w2h);
    cudaGetSymbolAddress((void**)&u,   g_u);
    cudaGetSymbolAddress((void**)&gp,  g_gp);
    cudaGetSymbolAddress((void**)&attn, g_attn);
    cudaGetSymbolAddress((void**)&nssp, g_nssp);
    cudaGetSymbolAddress((void**)&nss2, g_nss2);

    cudaFuncSetAttribute(gemm_h<false>, cudaFuncAttributeMaxDynamicSharedMemorySize, SMEM_T);
    cudaFuncSetAttribute(gemm_h<true >, cudaFuncAttributeMaxDynamicSharedMemorySize, SMEM_T);
    cudaFuncSetAttribute(gram_mma, cudaFuncAttributeMaxDynamicSharedMemorySize, GSMEM);

    cvt_w_kernel<<<dim3(64, 2), 256>>>((const float4*)Wq, (const float4*)Wk, wh);

    gemm_h<false><<<dim3(NCTA, 1, 2), 512, SMEM_T>>>(
        x1, wh, qh, x2, wh + Cn * Cn, kh, nullptr, nullptr, nssp);

    reduce_nss<<<dim3(Bn, 2), 256>>>(nssp, nss2);
    gram_mma<<<dim3(BHn, GSP), 256, GSMEM>>>(qh, kh, gp);
    softmax_kernel<<<BHn * Dn, 64>>>(gp, nss2, temperature, attn);

    fold1_kernel<<<dim3(BHn, 4), 256>>>(attn, Wv, u);
    fold2_kernel<<<dim3(4, 4, Bn), 256>>>(Wo, u, w2h);

    gemm_h<true><<<dim3(NCTA, 1, 1), 512, SMEM_T>>>(
        x2, w2h, nullptr, nullptr, nullptr, nullptr, bo, out, nullptr);
}

// round 16
// speedup vs baseline: 1.1470x; 1.0731x over previous
#include <cuda_runtime.h>
#include <cuda_fp16.h>
#include <math.h>
#include <stdint.h>

#define Bn 8
#define Nn 8192
#define Cn 256
#define Hn 4
#define Dn 64
#define BHn (Bn*Hn)
#define MTOT (Bn*Nn)
#define GSP 8
#define GSL (Nn/GSP)      // 1024
#define NCTA (MTOT/128)   // 512

// ---------------------------------------------------------------------------
// Scratch (__device__ globals; no allocation allowed)
// ---------------------------------------------------------------------------
__device__ __half g_qh [MTOT*Cn];
__device__ __half g_kh [MTOT*Cn];
__device__ __half g_x2h[MTOT*Cn];          // fp16 cache of x2, written by QK gemm
__device__ __half g_wh [2*Cn*Cn];
__device__ __half g_w2h[Bn*Cn*Cn];
__device__ float  g_u  [Bn*Cn*Cn];
__device__ float  g_gp [BHn*GSP*Dn*Dn];
__device__ float  g_attn[BHn*Dn*Dn];
__device__ float  g_nssp[2*NCTA*Cn];
__device__ float  g_nss2[2*Bn*Cn];

// ---------------------------------------------------------------------------
// Helpers
// ---------------------------------------------------------------------------
__device__ __forceinline__ uint32_t smem_u32(const void* p) {
    uint32_t a;
    asm("{ .reg .u64 t; cvta.to.shared.u64 t, %1; cvt.u32.u64 %0, t; }" : "=r"(a) : "l"(p));
    return a;
}
__device__ __forceinline__ void cp16(uint32_t sdst, const void* gsrc) {
    asm volatile("cp.async.cg.shared.global [%0], [%1], 16;"
                 :: "r"(sdst), "l"(__cvta_generic_to_global(gsrc)) : "memory");
}
#define CP_COMMIT() asm volatile("cp.async.commit_group;" ::: "memory")
#define CP_WAIT1()  asm volatile("cp.async.wait_group 1;" ::: "memory")
#define CP_WAIT2()  asm volatile("cp.async.wait_group 2;" ::: "memory")

#define LDSM4(r0, r1, r2, r3, addr) \
    asm volatile("ldmatrix.sync.aligned.m8n8.x4.shared.b16 {%0,%1,%2,%3}, [%4];" \
                 : "=r"(r0), "=r"(r1), "=r"(r2), "=r"(r3) : "r"(addr))
#define LDSM4T(r0, r1, r2, r3, addr) \
    asm volatile("ldmatrix.sync.aligned.m8n8.x4.trans.shared.b16 {%0,%1,%2,%3}, [%4];" \
                 : "=r"(r0), "=r"(r1), "=r"(r2), "=r"(r3) : "r"(addr))
#define LDSM2T(r0, r1, addr) \
    asm volatile("ldmatrix.sync.aligned.m8n8.x2.trans.shared.b16 {%0,%1}, [%2];" \
                 : "=r"(r0), "=r"(r1) : "r"(addr))

__device__ __forceinline__ void mma_f16(float* d, const uint32_t* a, const uint32_t* b) {
    asm volatile(
        "mma.sync.aligned.m16n8k16.row.col.f32.f16.f16.f32 "
        "{%0,%1,%2,%3}, {%4,%5,%6,%7}, {%8,%9}, {%0,%1,%2,%3};"
        : "+f"(d[0]), "+f"(d[1]), "+f"(d[2]), "+f"(d[3])
        : "r"(a[0]), "r"(a[1]), "r"(a[2]), "r"(a[3]), "r"(b[0]), "r"(b[1]));
}

// ---------------------------------------------------------------------------
// fp16 mma GEMM, CTA 128x256, 512 threads, warps 4Mx4N (32x64 each).
// K=256 in 4 chunks of 64, 3-stage pipeline (round-13 configuration).
// !OUTF32: A fp32 converted in-flight; z=1 also caches converted A to X2c.
//  OUTF32: A read as fp16 via cp.async (both operands async).
// ---------------------------------------------------------------------------
#define RSH 72
#define A_STG (128*RSH*2)               // 18432 B
#define B_STG (256*RSH*2)               // 36864 B
#define NST 3
#define SMEM_T (NST*(A_STG+B_STG) + 4096)

template<bool OUTF32>
__global__ void __launch_bounds__(512, 1) gemm_h(const float* __restrict__ X0,
                                                 const __half* __restrict__ W0,
                                                 __half* __restrict__ Yh0,
                                                 const float* __restrict__ X1,
                                                 const __half* __restrict__ W1,
                                                 __half* __restrict__ Yh1,
                                                 const float* __restrict__ bias,
                                                 float* __restrict__ Yf,
                                                 float* __restrict__ nssp,
                                                 const __half* __restrict__ Ah,
                                                 __half* __restrict__ X2c)
{
    extern __shared__ char sm[];
    const uint32_t sA = smem_u32(sm);
    const uint32_t sB = sA + NST * A_STG;
    float* part = reinterpret_cast<float*>(sm + NST * (A_STG + B_STG));

    const int tid  = threadIdx.x;
    const int wid  = tid >> 5, lane = tid & 31;
    const int wm   = wid & 3;
    const int wn   = wid >> 2;
    const int gid  = lane >> 2;
    const int tig  = lane & 3;
    const int m0   = blockIdx.x * 128;
    const int z    = OUTF32 ? 0 : blockIdx.z;

    const float* X = (!OUTF32 && z) ? X1 : X0;
    const __half* Wp = OUTF32 ? W0 + ((size_t)(m0 >> 13) << 16) : (z ? W1 : W0);
    __half* Yh = z ? Yh1 : Yh0;

    const int lrA = ((lane >> 3) & 1) * 8 + (lane & 7);
    const int lkA = (lane >> 4) * 8;
    const int lrB = (lane >> 4) * 8 + (lane & 7);
    const int lkB = ((lane >> 3) & 1) * 8;
    int aoffs[2], boffs[4];
    #pragma unroll
    for (int mt = 0; mt < 2; mt++) aoffs[mt] = (wm * 32 + mt * 16 + lrA) * RSH + lkA;
    #pragma unroll
    for (int nb = 0; nb < 4; nb++) boffs[nb] = (wn * 64 + nb * 16 + lrB) * RSH + lkB;

    auto ldA4 = [&](int k0, float4* p) {
        #pragma unroll
        for (int i = 0; i < 4; i++) {
            int g = tid + i * 512;
            p[i] = *reinterpret_cast<const float4*>(
                X + (size_t)(m0 + (g >> 4)) * Cn + k0 + (g & 15) * 4);
        }
    };
    auto stA4 = [&](int st, int k0, const float4* p) {
        #pragma unroll
        for (int i = 0; i < 4; i++) {
            int g = tid + i * 512;
            __half2 h0 = __floats2half2_rn(p[i].x, p[i].y);
            __half2 h1 = __floats2half2_rn(p[i].z, p[i].w);
            uint2 u;
            u.x = *reinterpret_cast<uint32_t*>(&h0);
            u.y = *reinterpret_cast<uint32_t*>(&h1);
            *reinterpret_cast<uint2*>(sm + st * A_STG + ((g >> 4) * RSH + (g & 15) * 4) * 2) = u;
            if (!OUTF32 && z)
                *reinterpret_cast<uint2*>(X2c + (size_t)(m0 + (g >> 4)) * Cn + k0 + (g & 15) * 4) = u;
        }
    };
    // fp16 A via cp.async (OUTF32 path): 128 rows x 64 halves = 1024 cp16
    auto loadAh = [&](int st, int k0) {
        #pragma unroll
        for (int i = 0; i < 2; i++) {
            int g = tid + i * 512;
            int r = g >> 3, kq = g & 7;
            cp16(sA + st * A_STG + (r * RSH + kq * 8) * 2,
                 Ah + (size_t)(m0 + r) * Cn + k0 + kq * 8);
        }
    };
    auto loadB = [&](int st, int k0) {
        #pragma unroll
        for (int i = 0; i < 4; i++) {
            int g = tid + i * 512;
            int r = g >> 3, kq = g & 7;
            cp16(sB + st * B_STG + (r * RSH + kq * 8) * 2,
                 Wp + (size_t)r * Cn + k0 + kq * 8);
        }
    };

    float acc[2][8][4] = {};

    if (OUTF32) {
        #pragma unroll
        for (int c = 0; c < 2; c++) {
            loadAh(c, c * 64);
            loadB(c, c * 64);
            CP_COMMIT();
        }
    } else {
        float4 p0[4], p1[4];
        ldA4(0, p0); ldA4(64, p1);
        stA4(0, 0, p0);  loadB(0, 0);  CP_COMMIT();
        stA4(1, 64, p1); loadB(1, 64); CP_COMMIT();
    }

    for (int ch = 0; ch < 4; ch++) {
        float4 pn[4];
        if (!OUTF32 && ch + 2 < 4) ldA4((ch + 2) * 64, pn);
        CP_WAIT1();
        __syncthreads();

        const int st = ch % 3;
        const uint32_t a0 = sA + st * A_STG;
        const uint32_t b0a = sB + st * B_STG;

        #pragma unroll
        for (int ks = 0; ks < 4; ks++) {
            uint32_t af[2][4];
            #pragma unroll
            for (int mt = 0; mt < 2; mt++)
                LDSM4(af[mt][0], af[mt][1], af[mt][2], af[mt][3],
                      a0 + (aoffs[mt] + ks * 16) * 2);
            uint32_t bf[8][2];
            #pragma unroll
            for (int nb = 0; nb < 4; nb++) {
                uint32_t r0, r1, r2, r3;
                LDSM4(r0, r1, r2, r3, b0a + (boffs[nb] + ks * 16) * 2);
                bf[nb * 2][0] = r0; bf[nb * 2][1] = r1;
                bf[nb * 2 + 1][0] = r2; bf[nb * 2 + 1][1] = r3;
            }
            #pragma unroll
            for (int mt = 0; mt < 2; mt++)
                #pragma unroll
                for (int nt = 0; nt < 8; nt++)
                    mma_f16(acc[mt][nt], af[mt], bf[nt]);
        }

        if (ch + 2 < 4) {
            if (OUTF32) loadAh((ch + 2) % 3, (ch + 2) * 64);
            else        stA4((ch + 2) % 3, (ch + 2) * 64, pn);
            loadB((ch + 2) % 3, (ch + 2) * 64);
        }
        CP_COMMIT();
    }

    // Output
    #pragma unroll
    for (int mt = 0; mt < 2; mt++) {
        const int m = m0 + wm * 32 + mt * 16 + gid;
        #pragma unroll
        for (int nt = 0; nt < 8; nt++) {
            const int cg = wn * 64 + nt * 8 + tig * 2;
            if (OUTF32) {
                float b0 = __ldg(bias + cg), b1 = __ldg(bias + cg + 1);
                float2 v0 = make_float2(acc[mt][nt][0] + b0, acc[mt][nt][1] + b1);
                float2 v1 = make_float2(acc[mt][nt][2] + b0, acc[mt][nt][3] + b1);
                *reinterpret_cast<float2*>(Yf + (size_t)m * Cn + cg)       = v0;
                *reinterpret_cast<float2*>(Yf + (size_t)(m + 8) * Cn + cg) = v1;
            } else {
                __half2 h0 = __floats2half2_rn(acc[mt][nt][0], acc[mt][nt][1]);
                __half2 h1 = __floats2half2_rn(acc[mt][nt][2], acc[mt][nt][3]);
                *reinterpret_cast<__half2*>(Yh + (size_t)m * Cn + cg)       = h0;
                *reinterpret_cast<__half2*>(Yh + (size_t)(m + 8) * Cn + cg) = h1;
            }
        }
    }

    if (!OUTF32) {
        float cs[8][2];
        #pragma unroll
        for (int nt = 0; nt < 8; nt++) {
            cs[nt][0] = acc[0][nt][0] * acc[0][nt][0] + acc[0][nt][2] * acc[0][nt][2]
                      + acc[1][nt][0] * acc[1][nt][0] + acc[1][nt][2] * acc[1][nt][2];
            cs[nt][1] = acc[0][nt][1] * acc[0][nt][1] + acc[0][nt][3] * acc[0][nt][3]
                      + acc[1][nt][1] * acc[1][nt][1] + acc[1][nt][3] * acc[1][nt][3];
        }
        #pragma unroll
        for (int nt = 0; nt < 8; nt++)
            #pragma unroll
            for (int j = 0; j < 2; j++) {
                cs[nt][j] += __shfl_xor_sync(0xffffffffu, cs[nt][j], 4);
                cs[nt][j] += __shfl_xor_sync(0xffffffffu, cs[nt][j], 8);
                cs[nt][j] += __shfl_xor_sync(0xffffffffu, cs[nt][j], 16);
            }
        if (gid == 0) {
            #pragma unroll
            for (int nt = 0; nt < 8; nt++) {
                part[wm * 256 + wn * 64 + nt * 8 + tig * 2]     = cs[nt][0];
                part[wm * 256 + wn * 64 + nt * 8 + tig * 2 + 1] = cs[nt][1];
            }
        }
        __syncthreads();
        if (tid < 256) {
            float s = part[tid] + part[256 + tid] + part[512 + tid] + part[768 + tid];
            nssp[((size_t)z * NCTA + blockIdx.x) * 256 + tid] = s;
        }
    }
}

// ---------------------------------------------------------------------------
// Reduce per-CTA sumsq partials -> per-batch norms (deterministic order)
// ---------------------------------------------------------------------------
__global__ void __launch_bounds__(256) reduce_nss(const float* __restrict__ nssp,
                                                  float* __restrict__ nss2)
{
    const int b = blockIdx.x, z = blockIdx.y, c = threadIdx.x;
    float s = 0.f;
    #pragma unroll 8
    for (int i = 0; i < 64; i++)
        s += nssp[((size_t)z * NCTA + b * 64 + i) * 256 + c];
    nss2[(z * Bn + b) * 256 + c] = s;
}

// ---------------------------------------------------------------------------
// Gram via fp16 mma with ldmatrix.trans — 4-stage cp.async, single barrier
// ---------------------------------------------------------------------------
#define GRS 72
#define GSTG (64*GRS*2)          // 9216 B per operand per stage
#define GSMEM (8*GSTG)           // 73728 B

__global__ void __launch_bounds__(256) gram_mma(const __half* __restrict__ Qh,
                                                const __half* __restrict__ Kh,
                                                float* __restrict__ Gp)
{
    extern __shared__ char smg[];
    const uint32_t sq = smem_u32(smg);
    const uint32_t sk = sq + 4 * GSTG;

    const int bh = blockIdx.x, sp = blockIdx.y;
    const int b = bh >> 2, h = bh & 3;
    const int tid = threadIdx.x;
    const int w = tid >> 5, lane = tid & 31;
    const int gid = lane >> 2, tig = lane & 3;
    const int t0 = sp * GSL;

    const __half* qb = Qh + ((size_t)b * Nn) * 256 + h * 64;
    const __half* kb = Kh + ((size_t)b * Nn) * 256 + h * 64;

    auto gload = [&](int st, int tc) {
        #pragma unroll
        for (int i = 0; i < 2; i++) {
            int g = tid + i * 256;
            int r = g >> 3, ck = g & 7;
            cp16(sq + st * GSTG + (r * GRS + ck * 8) * 2,
                 qb + (size_t)(t0 + tc + r) * 256 + ck * 8);
        }
        #pragma unroll
        for (int i = 0; i < 2; i++) {
            int g = tid + i * 256;
            int r = g >> 3, ck = g & 7;
            cp16(sk + st * GSTG + (r * GRS + ck * 8) * 2,
                 kb + (size_t)(t0 + tc + r) * 256 + ck * 8);
        }
    };

    const int aH = (((lane >> 4) & 1) * 8 + (lane & 7)) * GRS + ((lane >> 3) & 1) * 8;
    const int bH = (((lane >> 3) & 1) * 8 + (lane & 7)) * GRS + w * 8;

    float acc[4][4] = {};

    gload(0, 0);   CP_COMMIT();
    gload(1, 64);  CP_COMMIT();
    gload(2, 128); CP_COMMIT();

    const int NCH = GSL / 64;   // 16
    for (int c = 0; c < NCH; c++) {
        CP_WAIT2();
        __syncthreads();
        if (c + 3 < NCH) gload((c + 3) & 3, (c + 3) * 64);
        CP_COMMIT();

        const uint32_t aq = sq + (c & 3) * GSTG;
        const uint32_t ak = sk + (c & 3) * GSTG;

        #pragma unroll
        for (int st16 = 0; st16 < 4; st16++) {
            const int kb16 = st16 * 16;
            uint32_t bfr[2];
            LDSM2T(bfr[0], bfr[1], ak + (kb16 * GRS + bH) * 2);
            #pragma unroll
            for (int mt = 0; mt < 4; mt++) {
                uint32_t af[4];
                LDSM4T(af[0], af[1], af[2], af[3],
                       aq + (kb16 * GRS + aH + mt * 16) * 2);
                mma_f16(acc[mt], af, bfr);
            }
        }
    }

    float* g = Gp + (((size_t)bh * GSP + sp) << 12);
    #pragma unroll
    for (int mt = 0; mt < 4; mt++) {
        const int r0 = mt * 16 + gid;
        *reinterpret_cast<float2*>(g + r0 * 64 + w * 8 + tig * 2) =
            make_float2(acc[mt][0], acc[mt][1]);
        *reinterpret_cast<float2*>(g + (r0 + 8) * 64 + w * 8 + tig * 2) =
            make_float2(acc[mt][2], acc[mt][3]);
    }
}

// ---------------------------------------------------------------------------
// Weight f32 -> f16
// ---------------------------------------------------------------------------
__device__ __forceinline__ void cvt_store4(__half* dst, float4 v) {
    __half2 h0 = __floats2half2_rn(v.x, v.y);
    __half2 h1 = __floats2half2_rn(v.z, v.w);
    uint2 u;
    u.x = *reinterpret_cast<uint32_t*>(&h0);
    u.y = *reinterpret_cast<uint32_t*>(&h1);
    *reinterpret_cast<uint2*>(dst) = u;
}

__global__ void __launch_bounds__(256) cvt_w_kernel(const float4* __restrict__ wq,
                                                    const float4* __restrict__ wk,
                                                    __half* dst)
{
    const int n4 = (Cn * Cn) / 4;
    const float4* src = blockIdx.y == 0 ? wq : wk;
    __half* d = dst + (size_t)blockIdx.y * Cn * Cn;
    int i = blockIdx.x * 256 + threadIdx.x;
    if (i < n4) cvt_store4(d + i * 4, src[i]);
}

// ---------------------------------------------------------------------------
// Reduce gram partials, normalize * temperature, softmax
// ---------------------------------------------------------------------------
__global__ void __launch_bounds__(64) softmax_kernel(const float* __restrict__ Gp,
                                                     const float* __restrict__ nss2,
                                                     const float* __restrict__ temp,
                                                     float* __restrict__ A)
{
    const int r  = blockIdx.x;
    const int bh = r >> 6;
    const int dd = r & 63;
    const int b  = bh >> 2, h = bh & 3;
    const int e  = threadIdx.x;

    const float rq = 1.0f / fmaxf(sqrtf(nss2[(0 * Bn + b) * 256 + h * 64 + dd]), 1e-12f);
    const float rk = 1.0f / fmaxf(sqrtf(nss2[(1 * Bn + b) * 256 + h * 64 + e]), 1e-12f);

    float s = 0.f;
    #pragma unroll
    for (int sp = 0; sp < GSP; sp++)
        s += Gp[(((size_t)bh * GSP + sp) << 12) + dd * 64 + e];
    s *= rq * rk * temp[h];

    __shared__ float red[64];
    red[e] = s;
    __syncthreads();
    for (int st = 32; st > 0; st >>= 1) {
        if (e < st) red[e] = fmaxf(red[e], red[e + st]);
        __syncthreads();
    }
    float m = red[0];
    __syncthreads();
    float ex = __expf(s - m);
    red[e] = ex;
    __syncthreads();
    for (int st = 32; st > 0; st >>= 1) {
        if (e < st) red[e] += red[e + st];
        __syncthreads();
    }
    A[(size_t)bh * 4096 + dd * 64 + e] = ex / red[0];
}

// ---------------------------------------------------------------------------
// fold1: U_b[h*64+dd][k] = sum_e attn[bh][dd][e] * Wv[h*64+e][k]   (fp32)
// ---------------------------------------------------------------------------
__global__ void __launch_bounds__(256) fold1_kernel(const float* __restrict__ A,
                                                    const float* __restrict__ Wv,
                                                    float* __restrict__ U)
{
    __shared__ float at[64][65];
    __shared__ float wv[64][65];
    const int bh = blockIdx.x, kq = blockIdx.y;
    const int b = bh >> 2, h = bh & 3;
    const int tx = threadIdx.x & 15, ty = threadIdx.x >> 4;
    const int tid = threadIdx.x;

    const float* Ab = A + (size_t)bh * 4096;
    #pragma unroll
    for (int i = 0; i < 16; i++) {
        int idx = tid + i * 256;
        at[idx >> 6][idx & 63] = Ab[idx];
    }
    #pragma unroll
    for (int i = 0; i < 16; i++) {
        int idx = tid + i * 256;
        wv[idx >> 6][idx & 63] = Wv[(size_t)(h * 64 + (idx >> 6)) * 256 + kq * 64 + (idx & 63)];
    }
    __syncthreads();

    float acc[4][4] = {};
    #pragma unroll
    for (int e = 0; e < 64; e++) {
        float av[4], bv[4];
        #pragma unroll
        for (int i = 0; i < 4; i++) av[i] = at[ty * 4 + i][e];
        #pragma unroll
        for (int j = 0; j < 4; j++) bv[j] = wv[e][tx * 4 + j];
        #pragma unroll
        for (int i = 0; i < 4; i++)
            #pragma unroll
            for (int j = 0; j < 4; j++)
                acc[i][j] += av[i] * bv[j];
    }
    #pragma unroll
    for (int i = 0; i < 4; i++)
        #pragma unroll
        for (int j = 0; j < 4; j++)
            U[((size_t)b * 256 + h * 64 + ty * 4 + i) * 256 + kq * 64 + tx * 4 + j] = acc[i][j];
}

// ---------------------------------------------------------------------------
// fold2: W2_b[c][k] = sum_ddg Wo[c][ddg] * U_b[ddg][k]   -> fp16
// ---------------------------------------------------------------------------
__global__ void __launch_bounds__(256) fold2_kernel(const float* __restrict__ Wo,
                                                    const float* __restrict__ U,
                                                    __half* __restrict__ W2)
{
    __shared__ float ws[16][68];
    __shared__ float us[16][68];
    const int cq = blockIdx.x, kq = blockIdx.y, b = blockIdx.z;
    const int tid = threadIdx.x;
    const int tx = tid & 15, ty = tid >> 4;
    const int lrow = tid >> 2, lk4 = (tid & 3) * 4;
    const int krow = tid >> 4, kc4 = (tid & 15) * 4;

    const float* Ub = U + ((size_t)b << 16);
    float acc[4][4] = {};

    for (int k0 = 0; k0 < 256; k0 += 16) {
        float4 wv4 = *reinterpret_cast<const float4*>(
            Wo + (size_t)(cq * 64 + lrow) * 256 + k0 + lk4);
        float4 uv4 = *reinterpret_cast<const float4*>(
            Ub + (size_t)(k0 + krow) * 256 + kq * 64 + kc4);
        __syncthreads();
        ws[lk4+0][lrow] = wv4.x; ws[lk4+1][lrow] = wv4.y;
        ws[lk4+2][lrow] = wv4.z; ws[lk4+3][lrow] = wv4.w;
        *reinterpret_cast<float4*>(&us[krow][kc4]) = uv4;
        __syncthreads();
        #pragma unroll
        for (int kk = 0; kk < 16; kk++) {
            float4 a = *reinterpret_cast<const float4*>(&ws[kk][ty * 4]);
            float4 bb = *reinterpret_cast<const float4*>(&us[kk][tx * 4]);
            float av[4] = {a.x, a.y, a.z, a.w};
            float bv[4] = {bb.x, bb.y, bb.z, bb.w};
            #pragma unroll
            for (int i = 0; i < 4; i++)
                #pragma unroll
                for (int j = 0; j < 4; j++)
                    acc[i][j] += av[i] * bv[j];
        }
    }
    #pragma unroll
    for (int i = 0; i < 4; i++)
        #pragma unroll
        for (int j = 0; j < 4; j++)
            W2[((size_t)b << 16) + (size_t)(cq * 64 + ty * 4 + i) * 256 + kq * 64 + tx * 4 + j] =
                __float2half(acc[i][j]);
}

// ---------------------------------------------------------------------------
extern "C" void kernel_launch(void* const* d_in, const int* in_sizes, int n_in,
                              void* d_out, int out_size)
{
    (void)in_sizes; (void)n_in; (void)out_size;
    const float* x1 = (const float*)d_in[0];
    const float* x2 = (const float*)d_in[1];
    const float* Wq = (const float*)d_in[2];
    const float* Wk = (const float*)d_in[3];
    const float* Wv = (const float*)d_in[4];
    const float* Wo = (const float*)d_in[5];
    const float* bo = (const float*)d_in[6];
    const float* temperature = (const float*)d_in[7];
    float* out = (float*)d_out;

    __half *qh, *kh, *x2h, *wh, *w2h;
    float *u, *gp, *attn, *nssp, *nss2;
    cudaGetSymbolAddress((void**)&qh,  g_qh);
    cudaGetSymbolAddress((void**)&kh,  g_kh);
    cudaGetSymbolAddress((void**)&x2h, g_x2h);
    cudaGetSymbolAddress((void**)&wh,  g_wh);
    cudaGetSymbolAddress((void**)&w2h, g_w2h);
    cudaGetSymbolAddress((void**)&u,   g_u);
    cudaGetSymbolAddress((void**)&gp,  g_gp);
    cudaGetSymbolAddress((void**)&attn, g_attn);
    cudaGetSymbolAddress((void**)&nssp, g_nssp);
    cudaGetSymbolAddress((void**)&nss2, g_nss2);

    cudaFuncSetAttribute(gemm_h<false>, cudaFuncAttributeMaxDynamicSharedMemorySize, SMEM_T);
    cudaFuncSetAttribute(gemm_h<true >, cudaFuncAttributeMaxDynamicSharedMemorySize, SMEM_T);
    cudaFuncSetAttribute(gram_mma, cudaFuncAttributeMaxDynamicSharedMemorySize, GSMEM);

    cvt_w_kernel<<<dim3(64, 2), 256>>>((const float4*)Wq, (const float4*)Wk, wh);

    // q = x1 @ Wq^T, k = x2 @ Wk^T; z=1 also caches x2 as fp16 into x2h
    gemm_h<false><<<dim3(NCTA, 1, 2), 512, SMEM_T>>>(
        x1, wh, qh, x2, wh + Cn * Cn, kh, nullptr, nullptr, nssp, nullptr, x2h);

    reduce_nss<<<dim3(Bn, 2), 256>>>(nssp, nss2);
    gram_mma<<<dim3(BHn, GSP), 256, GSMEM>>>(qh, kh, gp);
    softmax_kernel<<<BHn * Dn, 64>>>(gp, nss2, temperature, attn);

    fold1_kernel<<<dim3(BHn, 4), 256>>>(attn, Wv, u);
    fold2_kernel<<<dim3(4, 4, Bn), 256>>>(Wo, u, w2h);

    // out = x2h @ W2_b^T + bo  (A read as fp16 via cp.async)
    gemm_h<true><<<dim3(NCTA, 1, 1), 512, SMEM_T>>>(
        nullptr, w2h, nullptr, nullptr, nullptr, nullptr, bo, out, nullptr, x2h, nullptr);
}

// round 17
// speedup vs baseline: 1.1606x; 1.0119x over previous
#include <cuda_runtime.h>
#include <cuda_fp16.h>
#include <math.h>
#include <stdint.h>

#define Bn 8
#define Nn 8192
#define Cn 256
#define Hn 4
#define Dn 64
#define BHn (Bn*Hn)
#define MTOT (Bn*Nn)
#define GSP 8
#define GSL (Nn/GSP)      // 1024
#define NCTA (MTOT/128)   // 512

// ---------------------------------------------------------------------------
// Scratch (__device__ globals; no allocation allowed)
// ---------------------------------------------------------------------------
__device__ __half g_qh [MTOT*Cn];
__device__ __half g_kh [MTOT*Cn];
__device__ __half g_x2h[MTOT*Cn];          // fp16 cache of x2, written by QK gemm
__device__ __half g_wh [2*Cn*Cn];
__device__ __half g_w2h[Bn*Cn*Cn];
__device__ float  g_u  [Bn*Cn*Cn];
__device__ float  g_gp [BHn*GSP*Dn*Dn];
__device__ float  g_attn[BHn*Dn*Dn];
__device__ float  g_nssp[2*NCTA*Cn];
__device__ float  g_nss2[2*Bn*Cn];

// ---------------------------------------------------------------------------
// Helpers
// ---------------------------------------------------------------------------
__device__ __forceinline__ uint32_t smem_u32(const void* p) {
    uint32_t a;
    asm("{ .reg .u64 t; cvta.to.shared.u64 t, %1; cvt.u32.u64 %0, t; }" : "=r"(a) : "l"(p));
    return a;
}
__device__ __forceinline__ void cp16(uint32_t sdst, const void* gsrc) {
    asm volatile("cp.async.cg.shared.global [%0], [%1], 16;"
                 :: "r"(sdst), "l"(__cvta_generic_to_global(gsrc)) : "memory");
}
#define CP_COMMIT() asm volatile("cp.async.commit_group;" ::: "memory")
#define CP_WAIT1()  asm volatile("cp.async.wait_group 1;" ::: "memory")
#define CP_WAIT2()  asm volatile("cp.async.wait_group 2;" ::: "memory")

#define LDSM4(r0, r1, r2, r3, addr) \
    asm volatile("ldmatrix.sync.aligned.m8n8.x4.shared.b16 {%0,%1,%2,%3}, [%4];" \
                 : "=r"(r0), "=r"(r1), "=r"(r2), "=r"(r3) : "r"(addr))
#define LDSM4T(r0, r1, r2, r3, addr) \
    asm volatile("ldmatrix.sync.aligned.m8n8.x4.trans.shared.b16 {%0,%1,%2,%3}, [%4];" \
                 : "=r"(r0), "=r"(r1), "=r"(r2), "=r"(r3) : "r"(addr))

__device__ __forceinline__ void mma_f16(float* d, const uint32_t* a, const uint32_t* b) {
    asm volatile(
        "mma.sync.aligned.m16n8k16.row.col.f32.f16.f16.f32 "
        "{%0,%1,%2,%3}, {%4,%5,%6,%7}, {%8,%9}, {%0,%1,%2,%3};"
        : "+f"(d[0]), "+f"(d[1]), "+f"(d[2]), "+f"(d[3])
        : "r"(a[0]), "r"(a[1]), "r"(a[2]), "r"(a[3]), "r"(b[0]), "r"(b[1]));
}

// ---------------------------------------------------------------------------
// fp16 mma GEMM, CTA 128x256, 512 threads, warps 4Mx4N (32x64 each).
// K=256 in 4 chunks of 64, 3-stage pipeline (round-13 configuration).
// !OUTF32: A fp32 converted in-flight; z=1 also caches converted A to X2c.
//  OUTF32: A read as fp16 via cp.async (both operands async).
// ---------------------------------------------------------------------------
#define RSH 72
#define A_STG (128*RSH*2)               // 18432 B
#define B_STG (256*RSH*2)               // 36864 B
#define NST 3
#define SMEM_T (NST*(A_STG+B_STG) + 4096)

template<bool OUTF32>
__global__ void __launch_bounds__(512, 1) gemm_h(const float* __restrict__ X0,
                                                 const __half* __restrict__ W0,
                                                 __half* __restrict__ Yh0,
                                                 const float* __restrict__ X1,
                                                 const __half* __restrict__ W1,
                                                 __half* __restrict__ Yh1,
                                                 const float* __restrict__ bias,
                                                 float* __restrict__ Yf,
                                                 float* __restrict__ nssp,
                                                 const __half* __restrict__ Ah,
                                                 __half* __restrict__ X2c)
{
    extern __shared__ char sm[];
    const uint32_t sA = smem_u32(sm);
    const uint32_t sB = sA + NST * A_STG;
    float* part = reinterpret_cast<float*>(sm + NST * (A_STG + B_STG));

    const int tid  = threadIdx.x;
    const int wid  = tid >> 5, lane = tid & 31;
    const int wm   = wid & 3;
    const int wn   = wid >> 2;
    const int gid  = lane >> 2;
    const int tig  = lane & 3;
    const int m0   = blockIdx.x * 128;
    const int z    = OUTF32 ? 0 : blockIdx.z;

    const float* X = (!OUTF32 && z) ? X1 : X0;
    const __half* Wp = OUTF32 ? W0 + ((size_t)(m0 >> 13) << 16) : (z ? W1 : W0);
    __half* Yh = z ? Yh1 : Yh0;

    const int lrA = ((lane >> 3) & 1) * 8 + (lane & 7);
    const int lkA = (lane >> 4) * 8;
    const int lrB = (lane >> 4) * 8 + (lane & 7);
    const int lkB = ((lane >> 3) & 1) * 8;
    int aoffs[2], boffs[4];
    #pragma unroll
    for (int mt = 0; mt < 2; mt++) aoffs[mt] = (wm * 32 + mt * 16 + lrA) * RSH + lkA;
    #pragma unroll
    for (int nb = 0; nb < 4; nb++) boffs[nb] = (wn * 64 + nb * 16 + lrB) * RSH + lkB;

    auto ldA4 = [&](int k0, float4* p) {
        #pragma unroll
        for (int i = 0; i < 4; i++) {
            int g = tid + i * 512;
            p[i] = *reinterpret_cast<const float4*>(
                X + (size_t)(m0 + (g >> 4)) * Cn + k0 + (g & 15) * 4);
        }
    };
    auto stA4 = [&](int st, int k0, const float4* p) {
        #pragma unroll
        for (int i = 0; i < 4; i++) {
            int g = tid + i * 512;
            __half2 h0 = __floats2half2_rn(p[i].x, p[i].y);
            __half2 h1 = __floats2half2_rn(p[i].z, p[i].w);
            uint2 u;
            u.x = *reinterpret_cast<uint32_t*>(&h0);
            u.y = *reinterpret_cast<uint32_t*>(&h1);
            *reinterpret_cast<uint2*>(sm + st * A_STG + ((g >> 4) * RSH + (g & 15) * 4) * 2) = u;
            if (!OUTF32 && z)
                *reinterpret_cast<uint2*>(X2c + (size_t)(m0 + (g >> 4)) * Cn + k0 + (g & 15) * 4) = u;
        }
    };
    auto loadAh = [&](int st, int k0) {
        #pragma unroll
        for (int i = 0; i < 2; i++) {
            int g = tid + i * 512;
            int r = g >> 3, kq = g & 7;
            cp16(sA + st * A_STG + (r * RSH + kq * 8) * 2,
                 Ah + (size_t)(m0 + r) * Cn + k0 + kq * 8);
        }
    };
    auto loadB = [&](int st, int k0) {
        #pragma unroll
        for (int i = 0; i < 4; i++) {
            int g = tid + i * 512;
            int r = g >> 3, kq = g & 7;
            cp16(sB + st * B_STG + (r * RSH + kq * 8) * 2,
                 Wp + (size_t)r * Cn + k0 + kq * 8);
        }
    };

    float acc[2][8][4] = {};

    if (OUTF32) {
        #pragma unroll
        for (int c = 0; c < 2; c++) {
            loadAh(c, c * 64);
            loadB(c, c * 64);
            CP_COMMIT();
        }
    } else {
        float4 p0[4], p1[4];
        ldA4(0, p0); ldA4(64, p1);
        stA4(0, 0, p0);  loadB(0, 0);  CP_COMMIT();
        stA4(1, 64, p1); loadB(1, 64); CP_COMMIT();
    }

    for (int ch = 0; ch < 4; ch++) {
        float4 pn[4];
        if (!OUTF32 && ch + 2 < 4) ldA4((ch + 2) * 64, pn);
        CP_WAIT1();
        __syncthreads();

        const int st = ch % 3;
        const uint32_t a0 = sA + st * A_STG;
        const uint32_t b0a = sB + st * B_STG;

        #pragma unroll
        for (int ks = 0; ks < 4; ks++) {
            uint32_t af[2][4];
            #pragma unroll
            for (int mt = 0; mt < 2; mt++)
                LDSM4(af[mt][0], af[mt][1], af[mt][2], af[mt][3],
                      a0 + (aoffs[mt] + ks * 16) * 2);
            uint32_t bf[8][2];
            #pragma unroll
            for (int nb = 0; nb < 4; nb++) {
                uint32_t r0, r1, r2, r3;
                LDSM4(r0, r1, r2, r3, b0a + (boffs[nb] + ks * 16) * 2);
                bf[nb * 2][0] = r0; bf[nb * 2][1] = r1;
                bf[nb * 2 + 1][0] = r2; bf[nb * 2 + 1][1] = r3;
            }
            #pragma unroll
            for (int mt = 0; mt < 2; mt++)
                #pragma unroll
                for (int nt = 0; nt < 8; nt++)
                    mma_f16(acc[mt][nt], af[mt], bf[nt]);
        }

        if (ch + 2 < 4) {
            if (OUTF32) loadAh((ch + 2) % 3, (ch + 2) * 64);
            else        stA4((ch + 2) % 3, (ch + 2) * 64, pn);
            loadB((ch + 2) % 3, (ch + 2) * 64);
        }
        CP_COMMIT();
    }

    // Output
    #pragma unroll
    for (int mt = 0; mt < 2; mt++) {
        const int m = m0 + wm * 32 + mt * 16 + gid;
        #pragma unroll
        for (int nt = 0; nt < 8; nt++) {
            const int cg = wn * 64 + nt * 8 + tig * 2;
            if (OUTF32) {
                float b0 = __ldg(bias + cg), b1 = __ldg(bias + cg + 1);
                float2 v0 = make_float2(acc[mt][nt][0] + b0, acc[mt][nt][1] + b1);
                float2 v1 = make_float2(acc[mt][nt][2] + b0, acc[mt][nt][3] + b1);
                *reinterpret_cast<float2*>(Yf + (size_t)m * Cn + cg)       = v0;
                *reinterpret_cast<float2*>(Yf + (size_t)(m + 8) * Cn + cg) = v1;
            } else {
                __half2 h0 = __floats2half2_rn(acc[mt][nt][0], acc[mt][nt][1]);
                __half2 h1 = __floats2half2_rn(acc[mt][nt][2], acc[mt][nt][3]);
                *reinterpret_cast<__half2*>(Yh + (size_t)m * Cn + cg)       = h0;
                *reinterpret_cast<__half2*>(Yh + (size_t)(m + 8) * Cn + cg) = h1;
            }
        }
    }

    if (!OUTF32) {
        float cs[8][2];
        #pragma unroll
        for (int nt = 0; nt < 8; nt++) {
            cs[nt][0] = acc[0][nt][0] * acc[0][nt][0] + acc[0][nt][2] * acc[0][nt][2]
                      + acc[1][nt][0] * acc[1][nt][0] + acc[1][nt][2] * acc[1][nt][2];
            cs[nt][1] = acc[0][nt][1] * acc[0][nt][1] + acc[0][nt][3] * acc[0][nt][3]
                      + acc[1][nt][1] * acc[1][nt][1] + acc[1][nt][3] * acc[1][nt][3];
        }
        #pragma unroll
        for (int nt = 0; nt < 8; nt++)
            #pragma unroll
            for (int j = 0; j < 2; j++) {
                cs[nt][j] += __shfl_xor_sync(0xffffffffu, cs[nt][j], 4);
                cs[nt][j] += __shfl_xor_sync(0xffffffffu, cs[nt][j], 8);
                cs[nt][j] += __shfl_xor_sync(0xffffffffu, cs[nt][j], 16);
            }
        if (gid == 0) {
            #pragma unroll
            for (int nt = 0; nt < 8; nt++) {
                part[wm * 256 + wn * 64 + nt * 8 + tig * 2]     = cs[nt][0];
                part[wm * 256 + wn * 64 + nt * 8 + tig * 2 + 1] = cs[nt][1];
            }
        }
        __syncthreads();
        if (tid < 256) {
            float s = part[tid] + part[256 + tid] + part[512 + tid] + part[768 + tid];
            nssp[((size_t)z * NCTA + blockIdx.x) * 256 + tid] = s;
        }
    }
}

// ---------------------------------------------------------------------------
// Reduce per-CTA sumsq partials -> per-batch norms (deterministic order)
// ---------------------------------------------------------------------------
__global__ void __launch_bounds__(256) reduce_nss(const float* __restrict__ nssp,
                                                  float* __restrict__ nss2)
{
    const int b = blockIdx.x, z = blockIdx.y, c = threadIdx.x;
    float s = 0.f;
    #pragma unroll 8
    for (int i = 0; i < 64; i++)
        s += nssp[((size_t)z * NCTA + b * 64 + i) * 256 + c];
    nss2[(z * Bn + b) * 256 + c] = s;
}

// ---------------------------------------------------------------------------
// Gram via fp16 mma with ldmatrix.trans — 4-stage cp.async, single barrier.
// Warp partition 2M x 4N: warp owns rows wm2*32 (2 m16 tiles) x cols wn2*16
// (2 n8 tiles). Cuts redundant A-fragment loads 8x -> 4x.
// ---------------------------------------------------------------------------
#define GRS 72
#define GSTG (64*GRS*2)          // 9216 B per operand per stage
#define GSMEM (8*GSTG)           // 73728 B

__global__ void __launch_bounds__(256) gram_mma(const __half* __restrict__ Qh,
                                                const __half* __restrict__ Kh,
                                                float* __restrict__ Gp)
{
    extern __shared__ char smg[];
    const uint32_t sq = smem_u32(smg);
    const uint32_t sk = sq + 4 * GSTG;

    const int bh = blockIdx.x, sp = blockIdx.y;
    const int b = bh >> 2, h = bh & 3;
    const int tid = threadIdx.x;
    const int w = tid >> 5, lane = tid & 31;
    const int gid = lane >> 2, tig = lane & 3;
    const int wm2 = w & 1;       // 2 M groups of 32 rows
    const int wn2 = w >> 1;      // 4 N groups of 16 cols
    const int t0 = sp * GSL;

    const __half* qb = Qh + ((size_t)b * Nn) * 256 + h * 64;
    const __half* kb = Kh + ((size_t)b * Nn) * 256 + h * 64;

    auto gload = [&](int st, int tc) {
        #pragma unroll
        for (int i = 0; i < 2; i++) {
            int g = tid + i * 256;
            int r = g >> 3, ck = g & 7;
            cp16(sq + st * GSTG + (r * GRS + ck * 8) * 2,
                 qb + (size_t)(t0 + tc + r) * 256 + ck * 8);
        }
        #pragma unroll
        for (int i = 0; i < 2; i++) {
            int g = tid + i * 256;
            int r = g >> 3, ck = g & 7;
            cp16(sk + st * GSTG + (r * GRS + ck * 8) * 2,
                 kb + (size_t)(t0 + tc + r) * 256 + ck * 8);
        }
    };

    // A (trans 16tok x 16chan): lanes 0-7:(tok0-7,c+0) 8-15:(tok0-7,c+8)
    //                           16-23:(tok8-15,c+0) 24-31:(tok8-15,c+8)
    const int aH = (((lane >> 4) & 1) * 8 + (lane & 7)) * GRS + ((lane >> 3) & 1) * 8;
    // B (trans 16tok x 16col): lanes 0-7:(tok0-7,c+0) 8-15:(tok8-15,c+0)
    //                          16-23:(tok0-7,c+8) 24-31:(tok8-15,c+8)
    // -> r0,r1 = k-halves of n8 tile (c+0); r2,r3 = n8 tile (c+8)
    const int bH = (((lane >> 3) & 1) * 8 + (lane & 7)) * GRS + (lane >> 4) * 8 + wn2 * 16;

    float acc[2][2][4] = {};

    gload(0, 0);   CP_COMMIT();
    gload(1, 64);  CP_COMMIT();
    gload(2, 128); CP_COMMIT();

    const int NCH = GSL / 64;   // 16
    for (int c = 0; c < NCH; c++) {
        CP_WAIT2();
        __syncthreads();
        if (c + 3 < NCH) gload((c + 3) & 3, (c + 3) * 64);
        CP_COMMIT();

        const uint32_t aq = sq + (c & 3) * GSTG;
        const uint32_t ak = sk + (c & 3) * GSTG;

        #pragma unroll
        for (int st16 = 0; st16 < 4; st16++) {
            const int kb16 = st16 * 16;
            uint32_t bfr[4];
            LDSM4T(bfr[0], bfr[1], bfr[2], bfr[3], ak + (kb16 * GRS + bH) * 2);
            #pragma unroll
            for (int mt = 0; mt < 2; mt++) {
                uint32_t af[4];
                LDSM4T(af[0], af[1], af[2], af[3],
                       aq + (kb16 * GRS + aH + (wm2 * 32 + mt * 16)) * 2);
                mma_f16(acc[mt][0], af, bfr);
                mma_f16(acc[mt][1], af, bfr + 2);
            }
        }
    }

    float* g = Gp + (((size_t)bh * GSP + sp) << 12);
    #pragma unroll
    for (int mt = 0; mt < 2; mt++) {
        const int r0 = wm2 * 32 + mt * 16 + gid;
        #pragma unroll
        for (int nt = 0; nt < 2; nt++) {
            const int c0 = wn2 * 16 + nt * 8 + tig * 2;
            *reinterpret_cast<float2*>(g + r0 * 64 + c0) =
                make_float2(acc[mt][nt][0], acc[mt][nt][1]);
            *reinterpret_cast<float2*>(g + (r0 + 8) * 64 + c0) =
                make_float2(acc[mt][nt][2], acc[mt][nt][3]);
        }
    }
}

// ---------------------------------------------------------------------------
// Weight f32 -> f16
// ---------------------------------------------------------------------------
__device__ __forceinline__ void cvt_store4(__half* dst, float4 v) {
    __half2 h0 = __floats2half2_rn(v.x, v.y);
    __half2 h1 = __floats2half2_rn(v.z, v.w);
    uint2 u;
    u.x = *reinterpret_cast<uint32_t*>(&h0);
    u.y = *reinterpret_cast<uint32_t*>(&h1);
    *reinterpret_cast<uint2*>(dst) = u;
}

__global__ void __launch_bounds__(256) cvt_w_kernel(const float4* __restrict__ wq,
                                                    const float4* __restrict__ wk,
                                                    __half* dst)
{
    const int n4 = (Cn * Cn) / 4;
    const float4* src = blockIdx.y == 0 ? wq : wk;
    __half* d = dst + (size_t)blockIdx.y * Cn * Cn;
    int i = blockIdx.x * 256 + threadIdx.x;
    if (i < n4) cvt_store4(d + i * 4, src[i]);
}

// ---------------------------------------------------------------------------
// Reduce gram partials, normalize * temperature, softmax
// ---------------------------------------------------------------------------
__global__ void __launch_bounds__(64) softmax_kernel(const float* __restrict__ Gp,
                                                     const float* __restrict__ nss2,
                                                     const float* __restrict__ temp,
                                                     float* __restrict__ A)
{
    const int r  = blockIdx.x;
    const int bh = r >> 6;
    const int dd = r & 63;
    const int b  = bh >> 2, h = bh & 3;
    const int e  = threadIdx.x;

    const float rq = 1.0f / fmaxf(sqrtf(nss2[(0 * Bn + b) * 256 + h * 64 + dd]), 1e-12f);
    const float rk = 1.0f / fmaxf(sqrtf(nss2[(1 * Bn + b) * 256 + h * 64 + e]), 1e-12f);

    float s = 0.f;
    #pragma unroll
    for (int sp = 0; sp < GSP; sp++)
        s += Gp[(((size_t)bh * GSP + sp) << 12) + dd * 64 + e];
    s *= rq * rk * temp[h];

    __shared__ float red[64];
    red[e] = s;
    __syncthreads();
    for (int st = 32; st > 0; st >>= 1) {
        if (e < st) red[e] = fmaxf(red[e], red[e + st]);
        __syncthreads();
    }
    float m = red[0];
    __syncthreads();
    float ex = __expf(s - m);
    red[e] = ex;
    __syncthreads();
    for (int st = 32; st > 0; st >>= 1) {
        if (e < st) red[e] += red[e + st];
        __syncthreads();
    }
    A[(size_t)bh * 4096 + dd * 64 + e] = ex / red[0];
}

// ---------------------------------------------------------------------------
// fold1: U_b[h*64+dd][k] = sum_e attn[bh][dd][e] * Wv[h*64+e][k]   (fp32)
// ---------------------------------------------------------------------------
__global__ void __launch_bounds__(256) fold1_kernel(const float* __restrict__ A,
                                                    const float* __restrict__ Wv,
                                                    float* __restrict__ U)
{
    __shared__ float at[64][65];
    __shared__ float wv[64][65];
    const int bh = blockIdx.x, kq = blockIdx.y;
    const int b = bh >> 2, h = bh & 3;
    const int tx = threadIdx.x & 15, ty = threadIdx.x >> 4;
    const int tid = threadIdx.x;

    const float* Ab = A + (size_t)bh * 4096;
    #pragma unroll
    for (int i = 0; i < 16; i++) {
        int idx = tid + i * 256;
        at[idx >> 6][idx & 63] = Ab[idx];
    }
    #pragma unroll
    for (int i = 0; i < 16; i++) {
        int idx = tid + i * 256;
        wv[idx >> 6][idx & 63] = Wv[(size_t)(h * 64 + (idx >> 6)) * 256 + kq * 64 + (idx & 63)];
    }
    __syncthreads();

    float acc[4][4] = {};
    #pragma unroll
    for (int e = 0; e < 64; e++) {
        float av[4], bv[4];
        #pragma unroll
        for (int i = 0; i < 4; i++) av[i] = at[ty * 4 + i][e];
        #pragma unroll
        for (int j = 0; j < 4; j++) bv[j] = wv[e][tx * 4 + j];
        #pragma unroll
        for (int i = 0; i < 4; i++)
            #pragma unroll
            for (int j = 0; j < 4; j++)
                acc[i][j] += av[i] * bv[j];
    }
    #pragma unroll
    for (int i = 0; i < 4; i++)
        #pragma unroll
        for (int j = 0; j < 4; j++)
            U[((size_t)b * 256 + h * 64 + ty * 4 + i) * 256 + kq * 64 + tx * 4 + j] = acc[i][j];
}

// ---------------------------------------------------------------------------
// fold2: W2_b[c][k] = sum_ddg Wo[c][ddg] * U_b[ddg][k]   -> fp16
// ---------------------------------------------------------------------------
__global__ void __launch_bounds__(256) fold2_kernel(const float* __restrict__ Wo,
                                                    const float* __restrict__ U,
                                                    __half* __restrict__ W2)
{
    __shared__ float ws[16][68];
    __shared__ float us[16][68];
    const int cq = blockIdx.x, kq = blockIdx.y, b = blockIdx.z;
    const int tid = threadIdx.x;
    const int tx = tid & 15, ty = tid >> 4;
    const int lrow = tid >> 2, lk4 = (tid & 3) * 4;
    const int krow = tid >> 4, kc4 = (tid & 15) * 4;

    const float* Ub = U + ((size_t)b << 16);
    float acc[4][4] = {};

    for (int k0 = 0; k0 < 256; k0 += 16) {
        float4 wv4 = *reinterpret_cast<const float4*>(
            Wo + (size_t)(cq * 64 + lrow) * 256 + k0 + lk4);
        float4 uv4 = *reinterpret_cast<const float4*>(
            Ub + (size_t)(k0 + krow) * 256 + kq * 64 + kc4);
        __syncthreads();
        ws[lk4+0][lrow] = wv4.x; ws[lk4+1][lrow] = wv4.y;
        ws[lk4+2][lrow] = wv4.z; ws[lk4+3][lrow] = wv4.w;
        *reinterpret_cast<float4*>(&us[krow][kc4]) = uv4;
        __syncthreads();
        #pragma unroll
        for (int kk = 0; kk < 16; kk++) {
            float4 a = *reinterpret_cast<const float4*>(&ws[kk][ty * 4]);
            float4 bb = *reinterpret_cast<const float4*>(&us[kk][tx * 4]);
            float av[4] = {a.x, a.y, a.z, a.w};
            float bv[4] = {bb.x, bb.y, bb.z, bb.w};
            #pragma unroll
            for (int i = 0; i < 4; i++)
                #pragma unroll
                for (int j = 0; j < 4; j++)
                    acc[i][j] += av[i] * bv[j];
        }
    }
    #pragma unroll
    for (int i = 0; i < 4; i++)
        #pragma unroll
        for (int j = 0; j < 4; j++)
            W2[((size_t)b << 16) + (size_t)(cq * 64 + ty * 4 + i) * 256 + kq * 64 + tx * 4 + j] =
                __float2half(acc[i][j]);
}

// ---------------------------------------------------------------------------
extern "C" void kernel_launch(void* const* d_in, const int* in_sizes, int n_in,
                              void* d_out, int out_size)
{
    (void)in_sizes; (void)n_in; (void)out_size;
    const float* x1 = (const float*)d_in[0];
    const float* x2 = (const float*)d_in[1];
    const float* Wq = (const float*)d_in[2];
    const float* Wk = (const float*)d_in[3];
    const float* Wv = (const float*)d_in[4];
    const float* Wo = (const float*)d_in[5];
    const float* bo = (const float*)d_in[6];
    const float* temperature = (const float*)d_in[7];
    float* out = (float*)d_out;

    __half *qh, *kh, *x2h, *wh, *w2h;
    float *u, *gp, *attn, *nssp, *nss2;
    cudaGetSymbolAddress((void**)&qh,  g_qh);
    cudaGetSymbolAddress((void**)&kh,  g_kh);
    cudaGetSymbolAddress((void**)&x2h, g_x2h);
    cudaGetSymbolAddress((void**)&wh,  g_wh);
    cudaGetSymbolAddress((void**)&w2h, g_w2h);
    cudaGetSymbolAddress((void**)&u,   g_u);
    cudaGetSymbolAddress((void**)&gp,  g_gp);
    cudaGetSymbolAddress((void**)&attn, g_attn);
    cudaGetSymbolAddress((void**)&nssp, g_nssp);
    cudaGetSymbolAddress((void**)&nss2, g_nss2);

    cudaFuncSetAttribute(gemm_h<false>, cudaFuncAttributeMaxDynamicSharedMemorySize, SMEM_T);
    cudaFuncSetAttribute(gemm_h<true >, cudaFuncAttributeMaxDynamicSharedMemorySize, SMEM_T);
    cudaFuncSetAttribute(gram_mma, cudaFuncAttributeMaxDynamicSharedMemorySize, GSMEM);

    cvt_w_kernel<<<dim3(64, 2), 256>>>((const float4*)Wq, (const float4*)Wk, wh);

    // q = x1 @ Wq^T, k = x2 @ Wk^T; z=1 also caches x2 as fp16 into x2h
    gemm_h<false><<<dim3(NCTA, 1, 2), 512, SMEM_T>>>(
        x1, wh, qh, x2, wh + Cn * Cn, kh, nullptr, nullptr, nssp, nullptr, x2h);

    reduce_nss<<<dim3(Bn, 2), 256>>>(nssp, nss2);
    gram_mma<<<dim3(BHn, GSP), 256, GSMEM>>>(qh, kh, gp);
    softmax_kernel<<<BHn * Dn, 64>>>(gp, nss2, temperature, attn);

    fold1_kernel<<<dim3(BHn, 4), 256>>>(attn, Wv, u);
    fold2_kernel<<<dim3(4, 4, Bn), 256>>>(Wo, u, w2h);

    // out = x2h @ W2_b^T + bo  (A read as fp16 via cp.async)
    gemm_h<true><<<dim3(NCTA, 1, 1), 512, SMEM_T>>>(
        nullptr, w2h, nullptr, nullptr, nullptr, nullptr, bo, out, nullptr, x2h, nullptr);
}